// round 10
// baseline (speedup 1.0000x reference)
#include <cuda_runtime.h>
#include <cuda_bf16.h>
#include <math.h>
#include <stdint.h>

#define B_   2
#define N_   2048
#define C_   1024
#define H_   16
#define D_   64
#define M_   (B_ * N_)      // 4096
#define QKVN 3072

// ---------------- mma.sync / ldmatrix helpers (portable PTX) ----------------
__device__ __forceinline__ uint32_t smem_u32(const void* p) {
    uint32_t a;
    asm("{ .reg .u64 t; cvta.to.shared.u64 t, %1; cvt.u32.u64 %0, t; }"
        : "=r"(a) : "l"(p));
    return a;
}
__device__ __forceinline__ uint32_t swz(uint32_t off) {  // SW128: bits[6:4] ^= bits[9:7]
    return off ^ ((off >> 3) & 0x70);
}
__device__ __forceinline__ void ldsm4(uint32_t* r, uint32_t addr) {
    asm volatile("ldmatrix.sync.aligned.m8n8.x4.shared.b16 {%0,%1,%2,%3}, [%4];"
                 : "=r"(r[0]), "=r"(r[1]), "=r"(r[2]), "=r"(r[3]) : "r"(addr));
}
__device__ __forceinline__ void ldsm4t(uint32_t* r, uint32_t addr) {
    asm volatile("ldmatrix.sync.aligned.m8n8.x4.trans.shared.b16 {%0,%1,%2,%3}, [%4];"
                 : "=r"(r[0]), "=r"(r[1]), "=r"(r[2]), "=r"(r[3]) : "r"(addr));
}
__device__ __forceinline__ void mma16816(float* d, const uint32_t* a,
                                         uint32_t b0, uint32_t b1) {
    asm volatile(
        "mma.sync.aligned.m16n8k16.row.col.f32.bf16.bf16.f32 "
        "{%0,%1,%2,%3}, {%4,%5,%6,%7}, {%8,%9}, {%0,%1,%2,%3};"
        : "+f"(d[0]), "+f"(d[1]), "+f"(d[2]), "+f"(d[3])
        : "r"(a[0]), "r"(a[1]), "r"(a[2]), "r"(a[3]), "r"(b0), "r"(b1));
}
__device__ __forceinline__ void cp16(uint32_t sdst, const void* gsrc) {
    asm volatile("cp.async.cg.shared.global [%0], [%1], 16;"
                 :: "r"(sdst), "l"(gsrc) : "memory");
}
#define CP_COMMIT() asm volatile("cp.async.commit_group;" ::: "memory")
#define CP_WAIT(n)  asm volatile("cp.async.wait_group %0;" :: "n"(n) : "memory")

// split two floats into packed (hi, lo) bf16x2 words
__device__ __forceinline__ void splitpack(float x, float y, uint32_t& Hw, uint32_t& Lw) {
    __nv_bfloat16 hx = __float2bfloat16(x), hy = __float2bfloat16(y);
    __nv_bfloat16 lx = __float2bfloat16(x - __bfloat162float(hx));
    __nv_bfloat16 ly = __float2bfloat16(y - __bfloat162float(hy));
    Hw = (uint32_t)__bfloat16_as_ushort(hx) | ((uint32_t)__bfloat16_as_ushort(hy) << 16);
    Lw = (uint32_t)__bfloat16_as_ushort(lx) | ((uint32_t)__bfloat16_as_ushort(ly) << 16);
}

// ---------------- scratch ----------------------------------------------------
__device__ float g_qkv[(size_t)M_ * QKVN];                  // 48 MB
__device__ __nv_bfloat16 g_xh[(size_t)M_ * C_];
__device__ __nv_bfloat16 g_xl[(size_t)M_ * C_];
__device__ __nv_bfloat16 g_wqh[(size_t)QKVN * C_];
__device__ __nv_bfloat16 g_wql[(size_t)QKVN * C_];
__device__ __nv_bfloat16 g_wph[(size_t)C_ * C_];
__device__ __nv_bfloat16 g_wpl[(size_t)C_ * C_];
__device__ __nv_bfloat16 g_qh[(size_t)B_ * H_ * N_ * D_];
__device__ __nv_bfloat16 g_ql[(size_t)B_ * H_ * N_ * D_];
__device__ __nv_bfloat16 g_kh[(size_t)B_ * H_ * N_ * D_];
__device__ __nv_bfloat16 g_kl[(size_t)B_ * H_ * N_ * D_];
__device__ __nv_bfloat16 g_vh[(size_t)B_ * H_ * N_ * D_];
__device__ __nv_bfloat16 g_vl[(size_t)B_ * H_ * N_ * D_];
__device__ __nv_bfloat16 g_aoh[(size_t)M_ * C_];
__device__ __nv_bfloat16 g_aol[(size_t)M_ * C_];

extern __shared__ __align__(1024) char dyn_sm[];

// ---------------- fp32 -> (hi, lo) bf16 split --------------------------------
__global__ void __launch_bounds__(256) cvt_hilo(
    const float4* __restrict__ src, uint2* __restrict__ hi,
    uint2* __restrict__ lo, int n4)
{
    int i = blockIdx.x * 256 + threadIdx.x;
    if (i >= n4) return;
    float4 v = src[i];
    uint2 Hv, Lv;
    splitpack(v.x, v.y, Hv.x, Lv.x);
    splitpack(v.z, v.w, Hv.y, Lv.y);
    hi[i] = Hv;
    lo[i] = Lv;
}

// ---------------- GEMM: C = A @ B^T (+bias), bf16 hi/lo 3-pass mma ----------
// 512 threads, 16 warps (wm 0-3 x wn 0-3), warp tile 32x32, block tile 128x128.
// cp.async 4-stage pipeline, kc=32, stage=32KB (4 ops x 8KB).
#define G_STAGE 32768
#define G_SMEM  (4 * G_STAGE)          // 131072

__global__ void __launch_bounds__(512, 1) gemm_mma(
    const __nv_bfloat16* __restrict__ Ah, const __nv_bfloat16* __restrict__ Al,
    const __nv_bfloat16* __restrict__ Bh, const __nv_bfloat16* __restrict__ Bl,
    const float* __restrict__ bias, float* __restrict__ C, int Nn)
{
    const int tid = threadIdx.x, lane = tid & 31, w = tid >> 5;  // 16 warps
    const int wm = w >> 2, wn = w & 3;
    const int bm = blockIdx.y << 7, bn = blockIdx.x << 7;
    const uint32_t sb = smem_u32(dyn_sm);

    float acc[2][4][4];                  // mt x (4 n8 tiles) x 4
#pragma unroll
    for (int mt = 0; mt < 2; mt++)
#pragma unroll
        for (int j = 0; j < 4; j++)
#pragma unroll
            for (int q = 0; q < 4; q++) acc[mt][j][q] = 0.0f;

    uint32_t offA[2], offB[2];
#pragma unroll
    for (int mt = 0; mt < 2; mt++) {
        const int rowA = wm * 32 + mt * 16 + (lane & 15);
        offA[mt] = rowA * 64 + (lane >> 4) * 16;
    }
#pragma unroll
    for (int np = 0; np < 2; np++) {
        const int nB = wn * 32 + np * 16 + (lane & 7) + ((lane >> 4) << 3);
        offB[np] = nB * 64 + ((lane >> 3) & 1) * 16;
    }

    // cp.async: 4 granules of 16B per thread per stage
    const __nv_bfloat16* srcs[4] = {Ah, Al, Bh, Bl};
    const __nv_bfloat16* gsrc[4];
    uint32_t sdst[4];
#pragma unroll
    for (int i = 0; i < 4; i++) {
        const int gid = tid + i * 512;
        const int op = gid >> 9, g = gid & 511;
        const int row = g >> 2, kg = g & 3;
        const int rb = (op < 2) ? bm : bn;
        gsrc[i] = srcs[op] + (size_t)(rb + row) * C_ + kg * 8;
        sdst[i] = op * 8192 + swz(row * 64 + kg * 16);
    }

    auto issue = [&](int c) {
        const uint32_t stb = sb + (c & 3) * G_STAGE;
#pragma unroll
        for (int i = 0; i < 4; i++)
            cp16(stb + sdst[i], gsrc[i] + c * 32);
    };

    issue(0); CP_COMMIT();
    issue(1); CP_COMMIT();
    issue(2); CP_COMMIT();

    for (int c = 0; c < 32; c++) {
        CP_WAIT(2);
        __syncthreads();
        if (c + 3 < 32) issue(c + 3);
        CP_COMMIT();

        const uint32_t stb = sb + (c & 3) * G_STAGE;
#pragma unroll
        for (int ks = 0; ks < 2; ks++) {
            uint32_t a_h[2][4], a_l[2][4];
#pragma unroll
            for (int mt = 0; mt < 2; mt++) {
                ldsm4(a_h[mt], stb + swz(offA[mt] + ks * 32));
                ldsm4(a_l[mt], stb + 8192 + swz(offA[mt] + ks * 32));
            }
#pragma unroll
            for (int np = 0; np < 2; np++) {
                uint32_t b_h[4], b_l[4];
                ldsm4(b_h, stb + 16384 + swz(offB[np] + ks * 32));
                ldsm4(b_l, stb + 24576 + swz(offB[np] + ks * 32));
#pragma unroll
                for (int mt = 0; mt < 2; mt++) {
                    mma16816(acc[mt][2 * np],     a_h[mt], b_h[0], b_h[1]);
                    mma16816(acc[mt][2 * np + 1], a_h[mt], b_h[2], b_h[3]);
                    mma16816(acc[mt][2 * np],     a_h[mt], b_l[0], b_l[1]);
                    mma16816(acc[mt][2 * np + 1], a_h[mt], b_l[2], b_l[3]);
                    mma16816(acc[mt][2 * np],     a_l[mt], b_h[0], b_h[1]);
                    mma16816(acc[mt][2 * np + 1], a_l[mt], b_h[2], b_h[3]);
                }
            }
        }
    }

#pragma unroll
    for (int mt = 0; mt < 2; mt++)
#pragma unroll
        for (int j = 0; j < 4; j++) {
            const int row = bm + wm * 32 + mt * 16 + (lane >> 2);
            const int col = bn + wn * 32 + j * 8 + ((lane & 3) << 1);
            const float b0 = bias ? bias[col] : 0.0f;
            const float b1 = bias ? bias[col + 1] : 0.0f;
            float2 v0 = make_float2(acc[mt][j][0] + b0, acc[mt][j][1] + b1);
            float2 v1 = make_float2(acc[mt][j][2] + b0, acc[mt][j][3] + b1);
            *(float2*)(C + (size_t)row * Nn + col) = v0;
            *(float2*)(C + (size_t)(row + 8) * Nn + col) = v1;
        }
}

// ---------------- RoPE + split -> q/k/v hi/lo bf16 [b][h][n][d] -------------
__global__ void __launch_bounds__(512) rope_split()
{
    const int m = blockIdx.x;
    const int b = m >> 11, n = m & (N_ - 1);
    const int h = threadIdx.x >> 5;
    const int i = threadIdx.x & 31;

    const float* row = g_qkv + (size_t)m * QKVN;
    const int c = h * D_;
    float q0 = row[c + i],            q1 = row[c + i + 32];
    float k0 = row[C_ + c + i],       k1 = row[C_ + c + i + 32];
    float v0 = row[2 * C_ + c + i],   v1 = row[2 * C_ + c + i + 32];

    float inv = exp2f(-11.0f * (float)i * (1.0f / 32.0f));  // 2048^(-i/32)
    float th = (float)n * inv;
    float cs = cosf(th), sn = sinf(th);

    float qa = q0 * cs - q1 * sn, qb = q1 * cs + q0 * sn;
    float ka = k0 * cs - k1 * sn, kb = k1 * cs + k0 * sn;

    size_t base = (((size_t)b * H_ + h) * N_ + n) * D_;
    const float vals[6] = {qa, qb, ka, kb, v0, v1};
    __nv_bfloat16* Hp[6] = {g_qh + base + i, g_qh + base + i + 32,
                            g_kh + base + i, g_kh + base + i + 32,
                            g_vh + base + i, g_vh + base + i + 32};
    __nv_bfloat16* Lp[6] = {g_ql + base + i, g_ql + base + i + 32,
                            g_kl + base + i, g_kl + base + i + 32,
                            g_vl + base + i, g_vl + base + i + 32};
#pragma unroll
    for (int t = 0; t < 6; t++) {
        __nv_bfloat16 hv = __float2bfloat16(vals[t]);
        *Hp[t] = hv;
        *Lp[t] = __float2bfloat16(vals[t] - __bfloat162float(hv));
    }
}

// ---------------- flash attention with mma.sync, BQ=128 BKV=64 --------------
// cp.async double-buffered K/V; 2 blocks/SM target (regs <= 128).
#define AT_KV0  32768
#define AT_SMEM (98304 + 512)
#define NKV     (N_ / 64)

__global__ void __launch_bounds__(256, 2) flash_attn_mma(const int* __restrict__ kpm)
{
    const int tid = threadIdx.x, lane = tid & 31, w = tid >> 5;
    const int b = blockIdx.z, h = blockIdx.y;
    const int q0 = blockIdx.x << 7;
    const uint32_t sb = smem_u32(dyn_sm);
    const size_t hoff = ((size_t)b * H_ + h) * N_ * D_;
    float* mbuf = (float*)(dyn_sm + 98304);

    // stage Q hi/lo [128][64]
    {
        const __nv_bfloat16* qsrc[2] = {g_qh + hoff + (size_t)q0 * D_,
                                        g_ql + hoff + (size_t)q0 * D_};
#pragma unroll
        for (int i = 0; i < 8; i++) {
            const int gid = tid + i * 256;
            const int op = gid >> 10, g = gid & 1023;
            const int row = g >> 3, dg = g & 7;
            uint4 v = *(const uint4*)(qsrc[op] + row * 64 + dg * 8);
            *(uint4*)(dyn_sm + op * 16384 + swz(row * 128 + dg * 16)) = v;
        }
    }

    const __nv_bfloat16* ksrc[4] = {g_kh + hoff, g_kl + hoff, g_vh + hoff, g_vl + hoff};
    const __nv_bfloat16* kgsrc[8];
    uint32_t ksdst[8];
#pragma unroll
    for (int i = 0; i < 8; i++) {
        const int gid = tid + i * 256;
        const int op = gid >> 9, g = gid & 511;
        const int row = g >> 3, dg = g & 7;
        kgsrc[i] = ksrc[op] + (size_t)row * D_ + dg * 8;
        ksdst[i] = AT_KV0 + op * 8192 + swz(row * 128 + dg * 16);
    }
    auto issue_kv = [&](int it) {
        const uint32_t stoff = (it & 1) * 32768;
#pragma unroll
        for (int i = 0; i < 8; i++)
            cp16(sb + stoff + ksdst[i], kgsrc[i] + it * 64 * D_);
        if (tid < 64)
            mbuf[(it & 1) * 64 + tid] =
                (kpm[b * N_ + it * 64 + tid] == 0) ? -1e9f : 0.0f;
    };

    issue_kv(0); CP_COMMIT();
    __syncthreads();

    // preload Q fragments
    uint32_t qfh[4][4], qfl[4][4];
    {
        const int rowQ = w * 16 + (lane & 15);
        const uint32_t base = rowQ * 128 + (lane >> 4) * 16;
#pragma unroll
        for (int ks = 0; ks < 4; ks++) {
            ldsm4(qfh[ks], sb + swz(base + ks * 32));
            ldsm4(qfl[ks], sb + 16384 + swz(base + ks * 32));
        }
    }

    float o[8][4];
#pragma unroll
    for (int j = 0; j < 8; j++)
#pragma unroll
        for (int q = 0; q < 4; q++) o[j][q] = 0.0f;
    float m0 = -INFINITY, m1 = -INFINITY, l0 = 0.0f, l1 = 0.0f;

    for (int it = 0; it < NKV; it++) {
        CP_WAIT(0);
        __syncthreads();
        if (it + 1 < NKV) issue_kv(it + 1);
        CP_COMMIT();

        const uint32_t kvb = sb + AT_KV0 + (it & 1) * 32768;
        const float* mb = mbuf + (it & 1) * 64;

        // ---- S = Q K^T (3-pass hi/lo), interleaved per np ----
        float s[8][4];
#pragma unroll
        for (int j = 0; j < 8; j++)
#pragma unroll
            for (int q = 0; q < 4; q++) s[j][q] = 0.0f;

#pragma unroll
        for (int ks = 0; ks < 4; ks++) {
#pragma unroll
            for (int np = 0; np < 4; np++) {
                const int nB = np * 16 + (lane & 7) + ((lane >> 4) << 3);
                const uint32_t ob = nB * 128 + ((lane >> 3) & 1) * 16 + ks * 32;
                uint32_t kb_h[4], kb_l[4];
                ldsm4(kb_h, kvb + swz(ob));
                ldsm4(kb_l, kvb + 8192 + swz(ob));
                mma16816(s[2 * np],     qfh[ks], kb_h[0], kb_h[1]);
                mma16816(s[2 * np + 1], qfh[ks], kb_h[2], kb_h[3]);
                mma16816(s[2 * np],     qfh[ks], kb_l[0], kb_l[1]);
                mma16816(s[2 * np + 1], qfh[ks], kb_l[2], kb_l[3]);
                mma16816(s[2 * np],     qfl[ks], kb_h[0], kb_h[1]);
                mma16816(s[2 * np + 1], qfl[ks], kb_h[2], kb_h[3]);
            }
        }

        // ---- scale + mask + online softmax ----
        const float scale = 0.125f;
        float mx0 = -INFINITY, mx1 = -INFINITY;
#pragma unroll
        for (int j = 0; j < 8; j++) {
            const int col = j * 8 + ((lane & 3) << 1);
            const float mb0 = mb[col], mb1 = mb[col + 1];
            s[j][0] = fmaf(s[j][0], scale, mb0);
            s[j][1] = fmaf(s[j][1], scale, mb1);
            s[j][2] = fmaf(s[j][2], scale, mb0);
            s[j][3] = fmaf(s[j][3], scale, mb1);
            mx0 = fmaxf(mx0, fmaxf(s[j][0], s[j][1]));
            mx1 = fmaxf(mx1, fmaxf(s[j][2], s[j][3]));
        }
        mx0 = fmaxf(mx0, __shfl_xor_sync(0xffffffffu, mx0, 1));
        mx0 = fmaxf(mx0, __shfl_xor_sync(0xffffffffu, mx0, 2));
        mx1 = fmaxf(mx1, __shfl_xor_sync(0xffffffffu, mx1, 1));
        mx1 = fmaxf(mx1, __shfl_xor_sync(0xffffffffu, mx1, 2));
        const float mn0 = fmaxf(m0, mx0), mn1 = fmaxf(m1, mx1);
        const float a0 = __expf(m0 - mn0), a1 = __expf(m1 - mn1);
        m0 = mn0; m1 = mn1;
        float s0 = 0.0f, s1 = 0.0f;
#pragma unroll
        for (int j = 0; j < 8; j++) {
            s[j][0] = __expf(s[j][0] - mn0);
            s[j][1] = __expf(s[j][1] - mn0);
            s[j][2] = __expf(s[j][2] - mn1);
            s[j][3] = __expf(s[j][3] - mn1);
            s0 += s[j][0] + s[j][1];
            s1 += s[j][2] + s[j][3];
        }
        s0 += __shfl_xor_sync(0xffffffffu, s0, 1);
        s0 += __shfl_xor_sync(0xffffffffu, s0, 2);
        s1 += __shfl_xor_sync(0xffffffffu, s1, 1);
        s1 += __shfl_xor_sync(0xffffffffu, s1, 2);
        l0 = l0 * a0 + s0;
        l1 = l1 * a1 + s1;
#pragma unroll
        for (int j = 0; j < 8; j++) {
            o[j][0] *= a0; o[j][1] *= a0;
            o[j][2] *= a1; o[j][3] *= a1;
        }

        // ---- pack P fragments (hi/lo) ----
        uint32_t ph[4][4], pl[4][4];
#pragma unroll
        for (int kt = 0; kt < 4; kt++) {
            const int t0 = 2 * kt, t1 = 2 * kt + 1;
            splitpack(s[t0][0], s[t0][1], ph[kt][0], pl[kt][0]);
            splitpack(s[t0][2], s[t0][3], ph[kt][1], pl[kt][1]);
            splitpack(s[t1][0], s[t1][1], ph[kt][2], pl[kt][2]);
            splitpack(s[t1][2], s[t1][3], ph[kt][3], pl[kt][3]);
        }

        // ---- O += P @ V (3-pass hi/lo), interleaved per dp ----
#pragma unroll
        for (int kt = 0; kt < 4; kt++) {
#pragma unroll
            for (int dp = 0; dp < 4; dp++) {
                const int kvr = kt * 16 + (lane & 15);
                const uint32_t ob = kvr * 128 + (dp * 2 + (lane >> 4)) * 16;
                uint32_t v_h[4], v_l[4];
                ldsm4t(v_h, kvb + 16384 + swz(ob));
                ldsm4t(v_l, kvb + 24576 + swz(ob));
                mma16816(o[2 * dp],     ph[kt], v_h[0], v_h[1]);
                mma16816(o[2 * dp + 1], ph[kt], v_h[2], v_h[3]);
                mma16816(o[2 * dp],     ph[kt], v_l[0], v_l[1]);
                mma16816(o[2 * dp + 1], ph[kt], v_l[2], v_l[3]);
                mma16816(o[2 * dp],     pl[kt], v_h[0], v_h[1]);
                mma16816(o[2 * dp + 1], pl[kt], v_h[2], v_h[3]);
            }
        }
    }

    // ---- normalize + hi/lo split -> g_aoh/g_aol ----
    const float li0 = 1.0f / l0, li1 = 1.0f / l1;
    const int n0 = q0 + w * 16 + (lane >> 2);
    const size_t ro0 = (size_t)(b * N_ + n0) * C_ + h * D_;
    const size_t ro1 = ro0 + (size_t)8 * C_;
#pragma unroll
    for (int j = 0; j < 8; j++) {
        const int col = j * 8 + ((lane & 3) << 1);
        uint32_t Hw, Lw;
        splitpack(o[j][0] * li0, o[j][1] * li0, Hw, Lw);
        *(uint32_t*)(g_aoh + ro0 + col) = Hw;
        *(uint32_t*)(g_aol + ro0 + col) = Lw;
        splitpack(o[j][2] * li1, o[j][3] * li1, Hw, Lw);
        *(uint32_t*)(g_aoh + ro1 + col) = Hw;
        *(uint32_t*)(g_aol + ro1 + col) = Lw;
    }
}

// ---------------------------------------------------------------------------
extern "C" void kernel_launch(void* const* d_in, const int* in_sizes, int n_in,
                              void* d_out, int out_size)
{
    const float* x      = (const float*)d_in[0];
    const float* w_qkv  = (const float*)d_in[1];
    const float* w_proj = (const float*)d_in[2];
    const float* b_proj = (const float*)d_in[3];
    const int*   kpm    = (const int*)d_in[4];
    float* out = (float*)d_out;

    float* qkv;
    __nv_bfloat16 *xh, *xl, *wqh, *wql, *wph, *wpl, *aoh, *aol;
    cudaGetSymbolAddress((void**)&qkv, g_qkv);
    cudaGetSymbolAddress((void**)&xh,  g_xh);
    cudaGetSymbolAddress((void**)&xl,  g_xl);
    cudaGetSymbolAddress((void**)&wqh, g_wqh);
    cudaGetSymbolAddress((void**)&wql, g_wql);
    cudaGetSymbolAddress((void**)&wph, g_wph);
    cudaGetSymbolAddress((void**)&wpl, g_wpl);
    cudaGetSymbolAddress((void**)&aoh, g_aoh);
    cudaGetSymbolAddress((void**)&aol, g_aol);

    // 0) split fp32 -> bf16 hi/lo
    cvt_hilo<<<(M_ * C_ / 4 + 255) / 256, 256>>>(
        (const float4*)x, (uint2*)xh, (uint2*)xl, M_ * C_ / 4);
    cvt_hilo<<<(QKVN * C_ / 4 + 255) / 256, 256>>>(
        (const float4*)w_qkv, (uint2*)wqh, (uint2*)wql, QKVN * C_ / 4);
    cvt_hilo<<<(C_ * C_ / 4 + 255) / 256, 256>>>(
        (const float4*)w_proj, (uint2*)wph, (uint2*)wpl, C_ * C_ / 4);

    // 1) qkv = x @ w_qkv^T
    cudaFuncSetAttribute(gemm_mma, cudaFuncAttributeMaxDynamicSharedMemorySize, G_SMEM);
    gemm_mma<<<dim3(QKVN / 128, M_ / 128), 512, G_SMEM>>>(
        xh, xl, wqh, wql, nullptr, qkv, QKVN);

    // 2) RoPE + split
    rope_split<<<M_, 512>>>();

    // 3) flash attention
    cudaFuncSetAttribute(flash_attn_mma, cudaFuncAttributeMaxDynamicSharedMemorySize,
                         AT_SMEM);
    flash_attn_mma<<<dim3(N_ / 128, H_, B_), 256, AT_SMEM>>>(kpm);

    // 4) out = ao @ w_proj^T + b_proj
    gemm_mma<<<dim3(C_ / 128, M_ / 128), 512, G_SMEM>>>(
        aoh, aol, wph, wpl, b_proj, out, C_);
}

// round 12
// speedup vs baseline: 1.3209x; 1.3209x over previous
#include <cuda_runtime.h>
#include <cuda_bf16.h>
#include <math.h>
#include <stdint.h>

#define B_   2
#define N_   2048
#define C_   1024
#define H_   16
#define D_   64
#define M_   (B_ * N_)      // 4096
#define QKVN 3072

// ---------------- mma.sync / ldmatrix helpers (portable PTX) ----------------
__device__ __forceinline__ uint32_t smem_u32(const void* p) {
    uint32_t a;
    asm("{ .reg .u64 t; cvta.to.shared.u64 t, %1; cvt.u32.u64 %0, t; }"
        : "=r"(a) : "l"(p));
    return a;
}
__device__ __forceinline__ uint32_t swz(uint32_t off) {  // SW128: bits[6:4] ^= bits[9:7]
    return off ^ ((off >> 3) & 0x70);
}
__device__ __forceinline__ void ldsm4(uint32_t* r, uint32_t addr) {
    asm volatile("ldmatrix.sync.aligned.m8n8.x4.shared.b16 {%0,%1,%2,%3}, [%4];"
                 : "=r"(r[0]), "=r"(r[1]), "=r"(r[2]), "=r"(r[3]) : "r"(addr));
}
__device__ __forceinline__ void ldsm4t(uint32_t* r, uint32_t addr) {
    asm volatile("ldmatrix.sync.aligned.m8n8.x4.trans.shared.b16 {%0,%1,%2,%3}, [%4];"
                 : "=r"(r[0]), "=r"(r[1]), "=r"(r[2]), "=r"(r[3]) : "r"(addr));
}
__device__ __forceinline__ void mma16816(float* d, const uint32_t* a,
                                         uint32_t b0, uint32_t b1) {
    asm volatile(
        "mma.sync.aligned.m16n8k16.row.col.f32.bf16.bf16.f32 "
        "{%0,%1,%2,%3}, {%4,%5,%6,%7}, {%8,%9}, {%0,%1,%2,%3};"
        : "+f"(d[0]), "+f"(d[1]), "+f"(d[2]), "+f"(d[3])
        : "r"(a[0]), "r"(a[1]), "r"(a[2]), "r"(a[3]), "r"(b0), "r"(b1));
}
__device__ __forceinline__ void cp16(uint32_t sdst, const void* gsrc) {
    asm volatile("cp.async.cg.shared.global [%0], [%1], 16;"
                 :: "r"(sdst), "l"(gsrc) : "memory");
}
#define CP_COMMIT() asm volatile("cp.async.commit_group;" ::: "memory")
#define CP_WAIT(n)  asm volatile("cp.async.wait_group %0;" :: "n"(n) : "memory")

// split two floats into packed (hi, lo) bf16x2 words
__device__ __forceinline__ void splitpack(float x, float y, uint32_t& Hw, uint32_t& Lw) {
    __nv_bfloat16 hx = __float2bfloat16(x), hy = __float2bfloat16(y);
    __nv_bfloat16 lx = __float2bfloat16(x - __bfloat162float(hx));
    __nv_bfloat16 ly = __float2bfloat16(y - __bfloat162float(hy));
    Hw = (uint32_t)__bfloat16_as_ushort(hx) | ((uint32_t)__bfloat16_as_ushort(hy) << 16);
    Lw = (uint32_t)__bfloat16_as_ushort(lx) | ((uint32_t)__bfloat16_as_ushort(ly) << 16);
}

// ---------------- scratch ----------------------------------------------------
__device__ float g_qkv[(size_t)M_ * QKVN];                  // 48 MB
__device__ __nv_bfloat16 g_xh[(size_t)M_ * C_];
__device__ __nv_bfloat16 g_xl[(size_t)M_ * C_];
__device__ __nv_bfloat16 g_wqh[(size_t)QKVN * C_];
__device__ __nv_bfloat16 g_wql[(size_t)QKVN * C_];
__device__ __nv_bfloat16 g_wph[(size_t)C_ * C_];
__device__ __nv_bfloat16 g_wpl[(size_t)C_ * C_];
__device__ __nv_bfloat16 g_qh[(size_t)B_ * H_ * N_ * D_];
__device__ __nv_bfloat16 g_ql[(size_t)B_ * H_ * N_ * D_];
__device__ __nv_bfloat16 g_kh[(size_t)B_ * H_ * N_ * D_];   // compacted keys
__device__ __nv_bfloat16 g_kl[(size_t)B_ * H_ * N_ * D_];
__device__ __nv_bfloat16 g_vh[(size_t)B_ * H_ * N_ * D_];
__device__ __nv_bfloat16 g_vl[(size_t)B_ * H_ * N_ * D_];
__device__ __nv_bfloat16 g_aoh[(size_t)M_ * C_];
__device__ __nv_bfloat16 g_aol[(size_t)M_ * C_];
__device__ int g_slot[M_];            // compact slot per (b,n), -1 if masked
__device__ int g_kvcnt[B_];           // valid-key count per batch

extern __shared__ __align__(1024) char dyn_sm[];

// ---------------- fp32 -> (hi, lo) bf16 split --------------------------------
__global__ void __launch_bounds__(256) cvt_hilo(
    const float4* __restrict__ src, uint2* __restrict__ hi,
    uint2* __restrict__ lo, int n4)
{
    int i = blockIdx.x * 256 + threadIdx.x;
    if (i >= n4) return;
    float4 v = src[i];
    uint2 Hv, Lv;
    splitpack(v.x, v.y, Hv.x, Lv.x);
    splitpack(v.z, v.w, Hv.y, Lv.y);
    hi[i] = Hv;
    lo[i] = Lv;
}

// ---------------- deterministic key compaction scan -------------------------
// one block per batch; 256 threads x 8 keys each; Hillis-Steele block scan.
__global__ void __launch_bounds__(256) compact_scan(const int* __restrict__ kpm)
{
    __shared__ int ps[256];
    const int b = blockIdx.x, t = threadIdx.x;
    int v[8], s = 0;
#pragma unroll
    for (int i = 0; i < 8; i++) {
        v[i] = (kpm[b * N_ + t * 8 + i] != 0);
        s += v[i];
    }
    ps[t] = s;
    __syncthreads();
    for (int off = 1; off < 256; off <<= 1) {
        int x = (t >= off) ? ps[t - off] : 0;
        __syncthreads();
        ps[t] += x;
        __syncthreads();
    }
    int base = ps[t] - s;   // exclusive prefix
#pragma unroll
    for (int i = 0; i < 8; i++) {
        g_slot[b * N_ + t * 8 + i] = v[i] ? base : -1;
        base += v[i];
    }
    if (t == 255) g_kvcnt[b] = ps[255];
}

// ---------------- GEMM: C = A @ B^T (+bias), bf16 hi/lo 3-pass mma ----------
// 512 threads, 16 warps, warp tile 32x32, block tile 128x128, cp.async 4-stage.
#define G_STAGE 32768
#define G_SMEM  (4 * G_STAGE)          // 131072

__global__ void __launch_bounds__(512, 1) gemm_mma(
    const __nv_bfloat16* __restrict__ Ah, const __nv_bfloat16* __restrict__ Al,
    const __nv_bfloat16* __restrict__ Bh, const __nv_bfloat16* __restrict__ Bl,
    const float* __restrict__ bias, float* __restrict__ C, int Nn)
{
    const int tid = threadIdx.x, lane = tid & 31, w = tid >> 5;
    const int wm = w >> 2, wn = w & 3;
    const int bm = blockIdx.y << 7, bn = blockIdx.x << 7;
    const uint32_t sb = smem_u32(dyn_sm);

    float acc[2][4][4];
#pragma unroll
    for (int mt = 0; mt < 2; mt++)
#pragma unroll
        for (int j = 0; j < 4; j++)
#pragma unroll
            for (int q = 0; q < 4; q++) acc[mt][j][q] = 0.0f;

    uint32_t offA[2], offB[2];
#pragma unroll
    for (int mt = 0; mt < 2; mt++) {
        const int rowA = wm * 32 + mt * 16 + (lane & 15);
        offA[mt] = rowA * 64 + (lane >> 4) * 16;
    }
#pragma unroll
    for (int np = 0; np < 2; np++) {
        const int nB = wn * 32 + np * 16 + (lane & 7) + ((lane >> 4) << 3);
        offB[np] = nB * 64 + ((lane >> 3) & 1) * 16;
    }

    const __nv_bfloat16* srcs[4] = {Ah, Al, Bh, Bl};
    const __nv_bfloat16* gsrc[4];
    uint32_t sdst[4];
#pragma unroll
    for (int i = 0; i < 4; i++) {
        const int gid = tid + i * 512;
        const int op = gid >> 9, g = gid & 511;
        const int row = g >> 2, kg = g & 3;
        const int rb = (op < 2) ? bm : bn;
        gsrc[i] = srcs[op] + (size_t)(rb + row) * C_ + kg * 8;
        sdst[i] = op * 8192 + swz(row * 64 + kg * 16);
    }

    auto issue = [&](int c) {
        const uint32_t stb = sb + (c & 3) * G_STAGE;
#pragma unroll
        for (int i = 0; i < 4; i++)
            cp16(stb + sdst[i], gsrc[i] + c * 32);
    };

    issue(0); CP_COMMIT();
    issue(1); CP_COMMIT();
    issue(2); CP_COMMIT();

    for (int c = 0; c < 32; c++) {
        CP_WAIT(2);
        __syncthreads();
        if (c + 3 < 32) issue(c + 3);
        CP_COMMIT();

        const uint32_t stb = sb + (c & 3) * G_STAGE;
#pragma unroll
        for (int ks = 0; ks < 2; ks++) {
            uint32_t a_h[2][4], a_l[2][4];
#pragma unroll
            for (int mt = 0; mt < 2; mt++) {
                ldsm4(a_h[mt], stb + swz(offA[mt] + ks * 32));
                ldsm4(a_l[mt], stb + 8192 + swz(offA[mt] + ks * 32));
            }
#pragma unroll
            for (int np = 0; np < 2; np++) {
                uint32_t b_h[4], b_l[4];
                ldsm4(b_h, stb + 16384 + swz(offB[np] + ks * 32));
                ldsm4(b_l, stb + 24576 + swz(offB[np] + ks * 32));
#pragma unroll
                for (int mt = 0; mt < 2; mt++) {
                    mma16816(acc[mt][2 * np],     a_h[mt], b_h[0], b_h[1]);
                    mma16816(acc[mt][2 * np + 1], a_h[mt], b_h[2], b_h[3]);
                    mma16816(acc[mt][2 * np],     a_h[mt], b_l[0], b_l[1]);
                    mma16816(acc[mt][2 * np + 1], a_h[mt], b_l[2], b_l[3]);
                    mma16816(acc[mt][2 * np],     a_l[mt], b_h[0], b_h[1]);
                    mma16816(acc[mt][2 * np + 1], a_l[mt], b_h[2], b_h[3]);
                }
            }
        }
    }

#pragma unroll
    for (int mt = 0; mt < 2; mt++)
#pragma unroll
        for (int j = 0; j < 4; j++) {
            const int row = bm + wm * 32 + mt * 16 + (lane >> 2);
            const int col = bn + wn * 32 + j * 8 + ((lane & 3) << 1);
            const float b0 = bias ? bias[col] : 0.0f;
            const float b1 = bias ? bias[col + 1] : 0.0f;
            float2 v0 = make_float2(acc[mt][j][0] + b0, acc[mt][j][1] + b1);
            float2 v1 = make_float2(acc[mt][j][2] + b0, acc[mt][j][3] + b1);
            *(float2*)(C + (size_t)row * Nn + col) = v0;
            *(float2*)(C + (size_t)(row + 8) * Nn + col) = v1;
        }
}

// ---------------- RoPE + split; K/V written to compacted slots --------------
__global__ void __launch_bounds__(512) rope_split()
{
    const int m = blockIdx.x;
    const int b = m >> 11, n = m & (N_ - 1);
    const int h = threadIdx.x >> 5;
    const int i = threadIdx.x & 31;
    const int slot = g_slot[m];

    const float* row = g_qkv + (size_t)m * QKVN;
    const int c = h * D_;
    float q0 = row[c + i],            q1 = row[c + i + 32];
    float k0 = row[C_ + c + i],       k1 = row[C_ + c + i + 32];
    float v0 = row[2 * C_ + c + i],   v1 = row[2 * C_ + c + i + 32];

    float inv = exp2f(-11.0f * (float)i * (1.0f / 32.0f));  // 2048^(-i/32)
    float th = (float)n * inv;
    float cs = cosf(th), sn = sinf(th);

    float qa = q0 * cs - q1 * sn, qb = q1 * cs + q0 * sn;
    float ka = k0 * cs - k1 * sn, kb = k1 * cs + k0 * sn;

    // Q at original row n
    {
        size_t base = (((size_t)b * H_ + h) * N_ + n) * D_;
        __nv_bfloat16 hv;
        hv = __float2bfloat16(qa);
        g_qh[base + i] = hv;
        g_ql[base + i] = __float2bfloat16(qa - __bfloat162float(hv));
        hv = __float2bfloat16(qb);
        g_qh[base + i + 32] = hv;
        g_ql[base + i + 32] = __float2bfloat16(qb - __bfloat162float(hv));
    }
    // K/V at compacted slot (skip masked keys entirely)
    if (slot >= 0) {
        size_t base = (((size_t)b * H_ + h) * N_ + slot) * D_;
        const float vals[4] = {ka, kb, v0, v1};
        __nv_bfloat16* Hp[4] = {g_kh + base + i, g_kh + base + i + 32,
                                g_vh + base + i, g_vh + base + i + 32};
        __nv_bfloat16* Lp[4] = {g_kl + base + i, g_kl + base + i + 32,
                                g_vl + base + i, g_vl + base + i + 32};
#pragma unroll
        for (int t = 0; t < 4; t++) {
            __nv_bfloat16 hv = __float2bfloat16(vals[t]);
            *Hp[t] = hv;
            *Lp[t] = __float2bfloat16(vals[t] - __bfloat162float(hv));
        }
    }
}

// ---------------- flash attention over COMPACTED keys, BQ=128 BKV=64 --------
#define AT_KV0  32768
#define AT_SMEM (98304 + 512)

__global__ void __launch_bounds__(256, 1) flash_attn_mma()
{
    const int tid = threadIdx.x, lane = tid & 31, w = tid >> 5;
    const int b = blockIdx.z, h = blockIdx.y;
    const int q0 = blockIdx.x << 7;
    const uint32_t sb = smem_u32(dyn_sm);
    const size_t hoff = ((size_t)b * H_ + h) * N_ * D_;
    float* mbuf = (float*)(dyn_sm + 98304);

    const int cnt = g_kvcnt[b];
    int nkv = (cnt + 63) >> 6;
    if (nkv < 1) nkv = 1;

    // stage Q hi/lo [128][64]
    {
        const __nv_bfloat16* qsrc[2] = {g_qh + hoff + (size_t)q0 * D_,
                                        g_ql + hoff + (size_t)q0 * D_};
#pragma unroll
        for (int i = 0; i < 8; i++) {
            const int gid = tid + i * 256;
            const int op = gid >> 10, g = gid & 1023;
            const int row = g >> 3, dg = g & 7;
            uint4 v = *(const uint4*)(qsrc[op] + row * 64 + dg * 8);
            *(uint4*)(dyn_sm + op * 16384 + swz(row * 128 + dg * 16)) = v;
        }
    }

    const __nv_bfloat16* ksrc[4] = {g_kh + hoff, g_kl + hoff, g_vh + hoff, g_vl + hoff};
    const __nv_bfloat16* kgsrc[8];
    uint32_t ksdst[8];
#pragma unroll
    for (int i = 0; i < 8; i++) {
        const int gid = tid + i * 256;
        const int op = gid >> 9, g = gid & 511;
        const int row = g >> 3, dg = g & 7;
        kgsrc[i] = ksrc[op] + (size_t)row * D_ + dg * 8;
        ksdst[i] = AT_KV0 + op * 8192 + swz(row * 128 + dg * 16);
    }
    auto issue_kv = [&](int it) {
        const uint32_t stoff = (it & 1) * 32768;
#pragma unroll
        for (int i = 0; i < 8; i++)
            cp16(sb + stoff + ksdst[i], kgsrc[i] + it * 64 * D_);
        if (tid < 64)
            mbuf[(it & 1) * 64 + tid] = (it * 64 + tid < cnt) ? 0.0f : -1e9f;
    };

    issue_kv(0); CP_COMMIT();
    __syncthreads();

    // preload Q fragments
    uint32_t qfh[4][4], qfl[4][4];
    {
        const int rowQ = w * 16 + (lane & 15);
        const uint32_t base = rowQ * 128 + (lane >> 4) * 16;
#pragma unroll
        for (int ks = 0; ks < 4; ks++) {
            ldsm4(qfh[ks], sb + swz(base + ks * 32));
            ldsm4(qfl[ks], sb + 16384 + swz(base + ks * 32));
        }
    }

    float o[8][4];
#pragma unroll
    for (int j = 0; j < 8; j++)
#pragma unroll
        for (int q = 0; q < 4; q++) o[j][q] = 0.0f;
    float m0 = -INFINITY, m1 = -INFINITY, l0 = 0.0f, l1 = 0.0f;

    for (int it = 0; it < nkv; it++) {
        CP_WAIT(0);
        __syncthreads();
        if (it + 1 < nkv) issue_kv(it + 1);
        CP_COMMIT();

        const uint32_t kvb = sb + AT_KV0 + (it & 1) * 32768;
        const float* mb = mbuf + (it & 1) * 64;

        // ---- S = Q K^T (3-pass hi/lo) ----
        float s[8][4];
#pragma unroll
        for (int j = 0; j < 8; j++)
#pragma unroll
            for (int q = 0; q < 4; q++) s[j][q] = 0.0f;

#pragma unroll
        for (int ks = 0; ks < 4; ks++) {
#pragma unroll
            for (int np = 0; np < 4; np++) {
                const int nB = np * 16 + (lane & 7) + ((lane >> 4) << 3);
                const uint32_t ob = nB * 128 + ((lane >> 3) & 1) * 16 + ks * 32;
                uint32_t kb_h[4], kb_l[4];
                ldsm4(kb_h, kvb + swz(ob));
                ldsm4(kb_l, kvb + 8192 + swz(ob));
                mma16816(s[2 * np],     qfh[ks], kb_h[0], kb_h[1]);
                mma16816(s[2 * np + 1], qfh[ks], kb_h[2], kb_h[3]);
                mma16816(s[2 * np],     qfh[ks], kb_l[0], kb_l[1]);
                mma16816(s[2 * np + 1], qfh[ks], kb_l[2], kb_l[3]);
                mma16816(s[2 * np],     qfl[ks], kb_h[0], kb_h[1]);
                mma16816(s[2 * np + 1], qfl[ks], kb_h[2], kb_h[3]);
            }
        }

        // ---- scale + tail mask + online softmax ----
        const float scale = 0.125f;
        float mx0 = -INFINITY, mx1 = -INFINITY;
#pragma unroll
        for (int j = 0; j < 8; j++) {
            const int col = j * 8 + ((lane & 3) << 1);
            const float mb0 = mb[col], mb1 = mb[col + 1];
            s[j][0] = fmaf(s[j][0], scale, mb0);
            s[j][1] = fmaf(s[j][1], scale, mb1);
            s[j][2] = fmaf(s[j][2], scale, mb0);
            s[j][3] = fmaf(s[j][3], scale, mb1);
            mx0 = fmaxf(mx0, fmaxf(s[j][0], s[j][1]));
            mx1 = fmaxf(mx1, fmaxf(s[j][2], s[j][3]));
        }
        mx0 = fmaxf(mx0, __shfl_xor_sync(0xffffffffu, mx0, 1));
        mx0 = fmaxf(mx0, __shfl_xor_sync(0xffffffffu, mx0, 2));
        mx1 = fmaxf(mx1, __shfl_xor_sync(0xffffffffu, mx1, 1));
        mx1 = fmaxf(mx1, __shfl_xor_sync(0xffffffffu, mx1, 2));
        const float mn0 = fmaxf(m0, mx0), mn1 = fmaxf(m1, mx1);
        const float a0 = __expf(m0 - mn0), a1 = __expf(m1 - mn1);
        m0 = mn0; m1 = mn1;
        float s0 = 0.0f, s1 = 0.0f;
#pragma unroll
        for (int j = 0; j < 8; j++) {
            s[j][0] = __expf(s[j][0] - mn0);
            s[j][1] = __expf(s[j][1] - mn0);
            s[j][2] = __expf(s[j][2] - mn1);
            s[j][3] = __expf(s[j][3] - mn1);
            s0 += s[j][0] + s[j][1];
            s1 += s[j][2] + s[j][3];
        }
        s0 += __shfl_xor_sync(0xffffffffu, s0, 1);
        s0 += __shfl_xor_sync(0xffffffffu, s0, 2);
        s1 += __shfl_xor_sync(0xffffffffu, s1, 1);
        s1 += __shfl_xor_sync(0xffffffffu, s1, 2);
        l0 = l0 * a0 + s0;
        l1 = l1 * a1 + s1;
#pragma unroll
        for (int j = 0; j < 8; j++) {
            o[j][0] *= a0; o[j][1] *= a0;
            o[j][2] *= a1; o[j][3] *= a1;
        }

        // ---- pack P fragments (hi/lo) ----
        uint32_t ph[4][4], pl[4][4];
#pragma unroll
        for (int kt = 0; kt < 4; kt++) {
            const int t0 = 2 * kt, t1 = 2 * kt + 1;
            splitpack(s[t0][0], s[t0][1], ph[kt][0], pl[kt][0]);
            splitpack(s[t0][2], s[t0][3], ph[kt][1], pl[kt][1]);
            splitpack(s[t1][0], s[t1][1], ph[kt][2], pl[kt][2]);
            splitpack(s[t1][2], s[t1][3], ph[kt][3], pl[kt][3]);
        }

        // ---- O += P @ V (3-pass hi/lo), V via ldmatrix.trans ----
#pragma unroll
        for (int kt = 0; kt < 4; kt++) {
#pragma unroll
            for (int dp = 0; dp < 4; dp++) {
                const int kvr = kt * 16 + (lane & 15);
                const uint32_t ob = kvr * 128 + (dp * 2 + (lane >> 4)) * 16;
                uint32_t v_h[4], v_l[4];
                ldsm4t(v_h, kvb + 16384 + swz(ob));
                ldsm4t(v_l, kvb + 24576 + swz(ob));
                mma16816(o[2 * dp],     ph[kt], v_h[0], v_h[1]);
                mma16816(o[2 * dp + 1], ph[kt], v_h[2], v_h[3]);
                mma16816(o[2 * dp],     ph[kt], v_l[0], v_l[1]);
                mma16816(o[2 * dp + 1], ph[kt], v_l[2], v_l[3]);
                mma16816(o[2 * dp],     pl[kt], v_h[0], v_h[1]);
                mma16816(o[2 * dp + 1], pl[kt], v_h[2], v_h[3]);
            }
        }
    }

    // ---- normalize + hi/lo split -> g_aoh/g_aol ----
    const float li0 = 1.0f / l0, li1 = 1.0f / l1;
    const int n0 = q0 + w * 16 + (lane >> 2);
    const size_t ro0 = (size_t)(b * N_ + n0) * C_ + h * D_;
    const size_t ro1 = ro0 + (size_t)8 * C_;
#pragma unroll
    for (int j = 0; j < 8; j++) {
        const int col = j * 8 + ((lane & 3) << 1);
        uint32_t Hw, Lw;
        splitpack(o[j][0] * li0, o[j][1] * li0, Hw, Lw);
        *(uint32_t*)(g_aoh + ro0 + col) = Hw;
        *(uint32_t*)(g_aol + ro0 + col) = Lw;
        splitpack(o[j][2] * li1, o[j][3] * li1, Hw, Lw);
        *(uint32_t*)(g_aoh + ro1 + col) = Hw;
        *(uint32_t*)(g_aol + ro1 + col) = Lw;
    }
}

// ---------------------------------------------------------------------------
extern "C" void kernel_launch(void* const* d_in, const int* in_sizes, int n_in,
                              void* d_out, int out_size)
{
    const float* x      = (const float*)d_in[0];
    const float* w_qkv  = (const float*)d_in[1];
    const float* w_proj = (const float*)d_in[2];
    const float* b_proj = (const float*)d_in[3];
    const int*   kpm    = (const int*)d_in[4];
    float* out = (float*)d_out;

    float* qkv;
    __nv_bfloat16 *xh, *xl, *wqh, *wql, *wph, *wpl, *aoh, *aol;
    cudaGetSymbolAddress((void**)&qkv, g_qkv);
    cudaGetSymbolAddress((void**)&xh,  g_xh);
    cudaGetSymbolAddress((void**)&xl,  g_xl);
    cudaGetSymbolAddress((void**)&wqh, g_wqh);
    cudaGetSymbolAddress((void**)&wql, g_wql);
    cudaGetSymbolAddress((void**)&wph, g_wph);
    cudaGetSymbolAddress((void**)&wpl, g_wpl);
    cudaGetSymbolAddress((void**)&aoh, g_aoh);
    cudaGetSymbolAddress((void**)&aol, g_aol);

    // 0) key compaction scan + fp32 -> bf16 hi/lo splits
    compact_scan<<<B_, 256>>>(kpm);
    cvt_hilo<<<(M_ * C_ / 4 + 255) / 256, 256>>>(
        (const float4*)x, (uint2*)xh, (uint2*)xl, M_ * C_ / 4);
    cvt_hilo<<<(QKVN * C_ / 4 + 255) / 256, 256>>>(
        (const float4*)w_qkv, (uint2*)wqh, (uint2*)wql, QKVN * C_ / 4);
    cvt_hilo<<<(C_ * C_ / 4 + 255) / 256, 256>>>(
        (const float4*)w_proj, (uint2*)wph, (uint2*)wpl, C_ * C_ / 4);

    // 1) qkv = x @ w_qkv^T
    cudaFuncSetAttribute(gemm_mma, cudaFuncAttributeMaxDynamicSharedMemorySize, G_SMEM);
    gemm_mma<<<dim3(QKVN / 128, M_ / 128), 512, G_SMEM>>>(
        xh, xl, wqh, wql, nullptr, qkv, QKVN);

    // 2) RoPE + split (K/V compacted)
    rope_split<<<M_, 512>>>();

    // 3) flash attention over compacted keys
    cudaFuncSetAttribute(flash_attn_mma, cudaFuncAttributeMaxDynamicSharedMemorySize,
                         AT_SMEM);
    flash_attn_mma<<<dim3(N_ / 128, H_, B_), 256, AT_SMEM>>>();

    // 4) out = ao @ w_proj^T + b_proj
    gemm_mma<<<dim3(C_ / 128, M_ / 128), 512, G_SMEM>>>(
        aoh, aol, wph, wpl, b_proj, out, C_);
}

// round 14
// speedup vs baseline: 1.5283x; 1.1570x over previous
#include <cuda_runtime.h>
#include <cuda_bf16.h>
#include <math.h>
#include <stdint.h>

#define B_   2
#define N_   2048
#define C_   1024
#define H_   16
#define D_   64
#define M_   (B_ * N_)      // 4096
#define QKVN 3072

// ---------------- mma.sync / ldmatrix helpers (portable PTX) ----------------
__device__ __forceinline__ uint32_t smem_u32(const void* p) {
    uint32_t a;
    asm("{ .reg .u64 t; cvta.to.shared.u64 t, %1; cvt.u32.u64 %0, t; }"
        : "=r"(a) : "l"(p));
    return a;
}
__device__ __forceinline__ uint32_t swz(uint32_t off) {  // SW128: bits[6:4] ^= bits[9:7]
    return off ^ ((off >> 3) & 0x70);
}
__device__ __forceinline__ void ldsm4(uint32_t* r, uint32_t addr) {
    asm volatile("ldmatrix.sync.aligned.m8n8.x4.shared.b16 {%0,%1,%2,%3}, [%4];"
                 : "=r"(r[0]), "=r"(r[1]), "=r"(r[2]), "=r"(r[3]) : "r"(addr));
}
__device__ __forceinline__ void ldsm4t(uint32_t* r, uint32_t addr) {
    asm volatile("ldmatrix.sync.aligned.m8n8.x4.trans.shared.b16 {%0,%1,%2,%3}, [%4];"
                 : "=r"(r[0]), "=r"(r[1]), "=r"(r[2]), "=r"(r[3]) : "r"(addr));
}
__device__ __forceinline__ void mma16816(float* d, const uint32_t* a,
                                         uint32_t b0, uint32_t b1) {
    asm volatile(
        "mma.sync.aligned.m16n8k16.row.col.f32.bf16.bf16.f32 "
        "{%0,%1,%2,%3}, {%4,%5,%6,%7}, {%8,%9}, {%0,%1,%2,%3};"
        : "+f"(d[0]), "+f"(d[1]), "+f"(d[2]), "+f"(d[3])
        : "r"(a[0]), "r"(a[1]), "r"(a[2]), "r"(a[3]), "r"(b0), "r"(b1));
}
__device__ __forceinline__ void cp16(uint32_t sdst, const void* gsrc) {
    asm volatile("cp.async.cg.shared.global [%0], [%1], 16;"
                 :: "r"(sdst), "l"(gsrc) : "memory");
}
#define CP_COMMIT() asm volatile("cp.async.commit_group;" ::: "memory")
#define CP_WAIT(n)  asm volatile("cp.async.wait_group %0;" :: "n"(n) : "memory")

// split two floats into packed (hi, lo) bf16x2 words
__device__ __forceinline__ void splitpack(float x, float y, uint32_t& Hw, uint32_t& Lw) {
    __nv_bfloat16 hx = __float2bfloat16(x), hy = __float2bfloat16(y);
    __nv_bfloat16 lx = __float2bfloat16(x - __bfloat162float(hx));
    __nv_bfloat16 ly = __float2bfloat16(y - __bfloat162float(hy));
    Hw = (uint32_t)__bfloat16_as_ushort(hx) | ((uint32_t)__bfloat16_as_ushort(hy) << 16);
    Lw = (uint32_t)__bfloat16_as_ushort(lx) | ((uint32_t)__bfloat16_as_ushort(ly) << 16);
}

// ---------------- scratch ----------------------------------------------------
// g_qkv is partitioned: [0 .. M*C) = Q gemm out; [M*C .. M*3C) = KV gemm out.
__device__ float g_qkv[(size_t)M_ * QKVN];                  // 48 MB
__device__ __nv_bfloat16 g_xh[(size_t)M_ * C_];
__device__ __nv_bfloat16 g_xl[(size_t)M_ * C_];
__device__ __nv_bfloat16 g_wqh[(size_t)QKVN * C_];
__device__ __nv_bfloat16 g_wql[(size_t)QKVN * C_];
__device__ __nv_bfloat16 g_wph[(size_t)C_ * C_];
__device__ __nv_bfloat16 g_wpl[(size_t)C_ * C_];
__device__ __nv_bfloat16 g_qh[(size_t)B_ * H_ * N_ * D_];
__device__ __nv_bfloat16 g_ql[(size_t)B_ * H_ * N_ * D_];
__device__ __nv_bfloat16 g_kh[(size_t)B_ * H_ * N_ * D_];   // compacted keys
__device__ __nv_bfloat16 g_kl[(size_t)B_ * H_ * N_ * D_];
__device__ __nv_bfloat16 g_vh[(size_t)B_ * H_ * N_ * D_];
__device__ __nv_bfloat16 g_vl[(size_t)B_ * H_ * N_ * D_];
__device__ __nv_bfloat16 g_aoh[(size_t)M_ * C_];
__device__ __nv_bfloat16 g_aol[(size_t)M_ * C_];
__device__ int g_slot[M_];            // compact slot per (b,n), -1 if masked
__device__ int g_inv[M_];             // absolute token row per (b, slot); pad -> b*N_
__device__ int g_kvcnt[B_];           // valid-key count per batch

extern __shared__ __align__(1024) char dyn_sm[];

// ---------------- fp32 -> (hi, lo) bf16 split --------------------------------
__global__ void __launch_bounds__(256) cvt_hilo(
    const float4* __restrict__ src, uint2* __restrict__ hi,
    uint2* __restrict__ lo, int n4)
{
    int i = blockIdx.x * 256 + threadIdx.x;
    if (i >= n4) return;
    float4 v = src[i];
    uint2 Hv, Lv;
    splitpack(v.x, v.y, Hv.x, Lv.x);
    splitpack(v.z, v.w, Hv.y, Lv.y);
    hi[i] = Hv;
    lo[i] = Lv;
}

// ---------------- deterministic key compaction scan -------------------------
// one block per batch; 256 threads x 8 keys each; Hillis-Steele block scan.
__global__ void __launch_bounds__(256) compact_scan(const int* __restrict__ kpm)
{
    __shared__ int ps[256];
    const int b = blockIdx.x, t = threadIdx.x;
    int v[8], s = 0;
#pragma unroll
    for (int i = 0; i < 8; i++) {
        v[i] = (kpm[b * N_ + t * 8 + i] != 0);
        s += v[i];
        g_inv[b * N_ + t * 8 + i] = b * N_;    // pad default (in-bounds row)
    }
    ps[t] = s;
    __syncthreads();
    for (int off = 1; off < 256; off <<= 1) {
        int x = (t >= off) ? ps[t - off] : 0;
        __syncthreads();
        ps[t] += x;
        __syncthreads();
    }
    int base = ps[t] - s;   // exclusive prefix
#pragma unroll
    for (int i = 0; i < 8; i++) {
        const int n = t * 8 + i;
        g_slot[b * N_ + n] = v[i] ? base : -1;
        if (v[i]) g_inv[b * N_ + base] = b * N_ + n;
        base += v[i];
    }
    if (t == 255) g_kvcnt[b] = ps[255];
}

// ---------------- GEMM: C = A @ B^T (+bias), bf16 hi/lo 3-pass mma ----------
// 512 threads, 16 warps, warp tile 32x32, block tile 128x128, cp.async 4-stage.
// Optional rowmap: A row = rowmap[out_row]; blocks fully past cnt exit early.
#define G_STAGE 32768
#define G_SMEM  (4 * G_STAGE)          // 131072

__global__ void __launch_bounds__(512, 1) gemm_mma(
    const __nv_bfloat16* __restrict__ Ah, const __nv_bfloat16* __restrict__ Al,
    const __nv_bfloat16* __restrict__ Bh, const __nv_bfloat16* __restrict__ Bl,
    const float* __restrict__ bias, float* __restrict__ C, int Nn,
    const int* __restrict__ rowmap, const int* __restrict__ cnts)
{
    const int tid = threadIdx.x, lane = tid & 31, w = tid >> 5;
    const int wm = w >> 2, wn = w & 3;
    const int bm = blockIdx.y << 7, bn = blockIdx.x << 7;
    if (rowmap && (bm & (N_ - 1)) >= cnts[bm >> 11]) return;
    const uint32_t sb = smem_u32(dyn_sm);

    float acc[2][4][4];
#pragma unroll
    for (int mt = 0; mt < 2; mt++)
#pragma unroll
        for (int j = 0; j < 4; j++)
#pragma unroll
            for (int q = 0; q < 4; q++) acc[mt][j][q] = 0.0f;

    uint32_t offA[2], offB[2];
#pragma unroll
    for (int mt = 0; mt < 2; mt++) {
        const int rowA = wm * 32 + mt * 16 + (lane & 15);
        offA[mt] = rowA * 64 + (lane >> 4) * 16;
    }
#pragma unroll
    for (int np = 0; np < 2; np++) {
        const int nB = wn * 32 + np * 16 + (lane & 7) + ((lane >> 4) << 3);
        offB[np] = nB * 64 + ((lane >> 3) & 1) * 16;
    }

    const __nv_bfloat16* srcs[4] = {Ah, Al, Bh, Bl};
    const __nv_bfloat16* gsrc[4];
    uint32_t sdst[4];
#pragma unroll
    for (int i = 0; i < 4; i++) {
        const int gid = tid + i * 512;
        const int op = gid >> 9, g = gid & 511;
        const int row = g >> 2, kg = g & 3;
        int arow;
        if (op < 2) arow = rowmap ? rowmap[bm + row] : (bm + row);
        else        arow = bn + row;
        gsrc[i] = srcs[op] + (size_t)arow * C_ + kg * 8;
        sdst[i] = op * 8192 + swz(row * 64 + kg * 16);
    }

    auto issue = [&](int c) {
        const uint32_t stb = sb + (c & 3) * G_STAGE;
#pragma unroll
        for (int i = 0; i < 4; i++)
            cp16(stb + sdst[i], gsrc[i] + c * 32);
    };

    issue(0); CP_COMMIT();
    issue(1); CP_COMMIT();
    issue(2); CP_COMMIT();

    for (int c = 0; c < 32; c++) {
        CP_WAIT(2);
        __syncthreads();
        if (c + 3 < 32) issue(c + 3);
        CP_COMMIT();

        const uint32_t stb = sb + (c & 3) * G_STAGE;
#pragma unroll
        for (int ks = 0; ks < 2; ks++) {
            uint32_t a_h[2][4], a_l[2][4];
#pragma unroll
            for (int mt = 0; mt < 2; mt++) {
                ldsm4(a_h[mt], stb + swz(offA[mt] + ks * 32));
                ldsm4(a_l[mt], stb + 8192 + swz(offA[mt] + ks * 32));
            }
#pragma unroll
            for (int np = 0; np < 2; np++) {
                uint32_t b_h[4], b_l[4];
                ldsm4(b_h, stb + 16384 + swz(offB[np] + ks * 32));
                ldsm4(b_l, stb + 24576 + swz(offB[np] + ks * 32));
#pragma unroll
                for (int mt = 0; mt < 2; mt++) {
                    mma16816(acc[mt][2 * np],     a_h[mt], b_h[0], b_h[1]);
                    mma16816(acc[mt][2 * np + 1], a_h[mt], b_h[2], b_h[3]);
                    mma16816(acc[mt][2 * np],     a_h[mt], b_l[0], b_l[1]);
                    mma16816(acc[mt][2 * np + 1], a_h[mt], b_l[2], b_l[3]);
                    mma16816(acc[mt][2 * np],     a_l[mt], b_h[0], b_h[1]);
                    mma16816(acc[mt][2 * np + 1], a_l[mt], b_h[2], b_h[3]);
                }
            }
        }
    }

#pragma unroll
    for (int mt = 0; mt < 2; mt++)
#pragma unroll
        for (int j = 0; j < 4; j++) {
            const int row = bm + wm * 32 + mt * 16 + (lane >> 2);
            const int col = bn + wn * 32 + j * 8 + ((lane & 3) << 1);
            const float b0 = bias ? bias[col] : 0.0f;
            const float b1 = bias ? bias[col + 1] : 0.0f;
            float2 v0 = make_float2(acc[mt][j][0] + b0, acc[mt][j][1] + b1);
            float2 v1 = make_float2(acc[mt][j][2] + b0, acc[mt][j][3] + b1);
            *(float2*)(C + (size_t)row * Nn + col) = v0;
            *(float2*)(C + (size_t)(row + 8) * Nn + col) = v1;
        }
}

// ---------------- RoPE for Q (all tokens) ------------------------------------
__global__ void __launch_bounds__(512) rope_q()
{
    const int m = blockIdx.x;
    const int b = m >> 11, n = m & (N_ - 1);
    const int h = threadIdx.x >> 5;
    const int i = threadIdx.x & 31;

    const float* row = g_qkv + (size_t)m * C_;           // Q section
    float q0 = row[h * D_ + i], q1 = row[h * D_ + i + 32];

    float inv = exp2f(-11.0f * (float)i * (1.0f / 32.0f));  // 2048^(-i/32)
    float th = (float)n * inv;
    float cs = cosf(th), sn = sinf(th);
    float qa = q0 * cs - q1 * sn, qb = q1 * cs + q0 * sn;

    size_t base = (((size_t)b * H_ + h) * N_ + n) * D_;
    __nv_bfloat16 hv;
    hv = __float2bfloat16(qa);
    g_qh[base + i] = hv;
    g_ql[base + i] = __float2bfloat16(qa - __bfloat162float(hv));
    hv = __float2bfloat16(qb);
    g_qh[base + i + 32] = hv;
    g_ql[base + i + 32] = __float2bfloat16(qb - __bfloat162float(hv));
}

// ---------------- RoPE for K + split V (compacted rows only) -----------------
__global__ void __launch_bounds__(512) rope_kv()
{
    const int m = blockIdx.x;                 // b * N_ + slot
    const int b = m >> 11, slot = m & (N_ - 1);
    if (slot >= g_kvcnt[b]) return;
    const int n = g_inv[m] & (N_ - 1);        // original token position
    const int h = threadIdx.x >> 5;
    const int i = threadIdx.x & 31;

    const float* row = g_qkv + (size_t)M_ * C_ + (size_t)m * 2048;  // KV section
    float k0 = row[h * D_ + i],        k1 = row[h * D_ + i + 32];
    float v0 = row[C_ + h * D_ + i],   v1 = row[C_ + h * D_ + i + 32];

    float inv = exp2f(-11.0f * (float)i * (1.0f / 32.0f));
    float th = (float)n * inv;
    float cs = cosf(th), sn = sinf(th);
    float ka = k0 * cs - k1 * sn, kb = k1 * cs + k0 * sn;

    size_t base = (((size_t)b * H_ + h) * N_ + slot) * D_;
    const float vals[4] = {ka, kb, v0, v1};
    __nv_bfloat16* Hp[4] = {g_kh + base + i, g_kh + base + i + 32,
                            g_vh + base + i, g_vh + base + i + 32};
    __nv_bfloat16* Lp[4] = {g_kl + base + i, g_kl + base + i + 32,
                            g_vl + base + i, g_vl + base + i + 32};
#pragma unroll
    for (int t = 0; t < 4; t++) {
        __nv_bfloat16 hv = __float2bfloat16(vals[t]);
        *Hp[t] = hv;
        *Lp[t] = __float2bfloat16(vals[t] - __bfloat162float(hv));
    }
}

// ---------------- flash attention over COMPACTED keys, BQ=128 BKV=64 --------
#define AT_KV0  32768
#define AT_SMEM (98304 + 512)

__global__ void __launch_bounds__(256, 1) flash_attn_mma()
{
    const int tid = threadIdx.x, lane = tid & 31, w = tid >> 5;
    const int b = blockIdx.z, h = blockIdx.y;
    const int q0 = blockIdx.x << 7;
    const uint32_t sb = smem_u32(dyn_sm);
    const size_t hoff = ((size_t)b * H_ + h) * N_ * D_;
    float* mbuf = (float*)(dyn_sm + 98304);

    const int cnt = g_kvcnt[b];
    int nkv = (cnt + 63) >> 6;
    if (nkv < 1) nkv = 1;

    // stage Q hi/lo [128][64]
    {
        const __nv_bfloat16* qsrc[2] = {g_qh + hoff + (size_t)q0 * D_,
                                        g_ql + hoff + (size_t)q0 * D_};
#pragma unroll
        for (int i = 0; i < 8; i++) {
            const int gid = tid + i * 256;
            const int op = gid >> 10, g = gid & 1023;
            const int row = g >> 3, dg = g & 7;
            uint4 v = *(const uint4*)(qsrc[op] + row * 64 + dg * 8);
            *(uint4*)(dyn_sm + op * 16384 + swz(row * 128 + dg * 16)) = v;
        }
    }

    const __nv_bfloat16* ksrc[4] = {g_kh + hoff, g_kl + hoff, g_vh + hoff, g_vl + hoff};
    const __nv_bfloat16* kgsrc[8];
    uint32_t ksdst[8];
#pragma unroll
    for (int i = 0; i < 8; i++) {
        const int gid = tid + i * 256;
        const int op = gid >> 9, g = gid & 511;
        const int row = g >> 3, dg = g & 7;
        kgsrc[i] = ksrc[op] + (size_t)row * D_ + dg * 8;
        ksdst[i] = AT_KV0 + op * 8192 + swz(row * 128 + dg * 16);
    }
    auto issue_kv = [&](int it) {
        const uint32_t stoff = (it & 1) * 32768;
#pragma unroll
        for (int i = 0; i < 8; i++)
            cp16(sb + stoff + ksdst[i], kgsrc[i] + it * 64 * D_);
        if (tid < 64)
            mbuf[(it & 1) * 64 + tid] = (it * 64 + tid < cnt) ? 0.0f : -1e9f;
    };

    issue_kv(0); CP_COMMIT();
    __syncthreads();

    // preload Q fragments
    uint32_t qfh[4][4], qfl[4][4];
    {
        const int rowQ = w * 16 + (lane & 15);
        const uint32_t base = rowQ * 128 + (lane >> 4) * 16;
#pragma unroll
        for (int ks = 0; ks < 4; ks++) {
            ldsm4(qfh[ks], sb + swz(base + ks * 32));
            ldsm4(qfl[ks], sb + 16384 + swz(base + ks * 32));
        }
    }

    float o[8][4];
#pragma unroll
    for (int j = 0; j < 8; j++)
#pragma unroll
        for (int q = 0; q < 4; q++) o[j][q] = 0.0f;
    float m0 = -INFINITY, m1 = -INFINITY, l0 = 0.0f, l1 = 0.0f;

    for (int it = 0; it < nkv; it++) {
        CP_WAIT(0);
        __syncthreads();
        if (it + 1 < nkv) issue_kv(it + 1);
        CP_COMMIT();

        const uint32_t kvb = sb + AT_KV0 + (it & 1) * 32768;
        const float* mb = mbuf + (it & 1) * 64;

        // ---- S = Q K^T (3-pass hi/lo) ----
        float s[8][4];
#pragma unroll
        for (int j = 0; j < 8; j++)
#pragma unroll
            for (int q = 0; q < 4; q++) s[j][q] = 0.0f;

#pragma unroll
        for (int ks = 0; ks < 4; ks++) {
#pragma unroll
            for (int np = 0; np < 4; np++) {
                const int nB = np * 16 + (lane & 7) + ((lane >> 4) << 3);
                const uint32_t ob = nB * 128 + ((lane >> 3) & 1) * 16 + ks * 32;
                uint32_t kb_h[4], kb_l[4];
                ldsm4(kb_h, kvb + swz(ob));
                ldsm4(kb_l, kvb + 8192 + swz(ob));
                mma16816(s[2 * np],     qfh[ks], kb_h[0], kb_h[1]);
                mma16816(s[2 * np + 1], qfh[ks], kb_h[2], kb_h[3]);
                mma16816(s[2 * np],     qfh[ks], kb_l[0], kb_l[1]);
                mma16816(s[2 * np + 1], qfh[ks], kb_l[2], kb_l[3]);
                mma16816(s[2 * np],     qfl[ks], kb_h[0], kb_h[1]);
                mma16816(s[2 * np + 1], qfl[ks], kb_h[2], kb_h[3]);
            }
        }

        // ---- scale + tail mask + online softmax ----
        const float scale = 0.125f;
        float mx0 = -INFINITY, mx1 = -INFINITY;
#pragma unroll
        for (int j = 0; j < 8; j++) {
            const int col = j * 8 + ((lane & 3) << 1);
            const float mb0 = mb[col], mb1 = mb[col + 1];
            s[j][0] = fmaf(s[j][0], scale, mb0);
            s[j][1] = fmaf(s[j][1], scale, mb1);
            s[j][2] = fmaf(s[j][2], scale, mb0);
            s[j][3] = fmaf(s[j][3], scale, mb1);
            mx0 = fmaxf(mx0, fmaxf(s[j][0], s[j][1]));
            mx1 = fmaxf(mx1, fmaxf(s[j][2], s[j][3]));
        }
        mx0 = fmaxf(mx0, __shfl_xor_sync(0xffffffffu, mx0, 1));
        mx0 = fmaxf(mx0, __shfl_xor_sync(0xffffffffu, mx0, 2));
        mx1 = fmaxf(mx1, __shfl_xor_sync(0xffffffffu, mx1, 1));
        mx1 = fmaxf(mx1, __shfl_xor_sync(0xffffffffu, mx1, 2));
        const float mn0 = fmaxf(m0, mx0), mn1 = fmaxf(m1, mx1);
        const float a0 = __expf(m0 - mn0), a1 = __expf(m1 - mn1);
        m0 = mn0; m1 = mn1;
        float s0 = 0.0f, s1 = 0.0f;
#pragma unroll
        for (int j = 0; j < 8; j++) {
            s[j][0] = __expf(s[j][0] - mn0);
            s[j][1] = __expf(s[j][1] - mn0);
            s[j][2] = __expf(s[j][2] - mn1);
            s[j][3] = __expf(s[j][3] - mn1);
            s0 += s[j][0] + s[j][1];
            s1 += s[j][2] + s[j][3];
        }
        s0 += __shfl_xor_sync(0xffffffffu, s0, 1);
        s0 += __shfl_xor_sync(0xffffffffu, s0, 2);
        s1 += __shfl_xor_sync(0xffffffffu, s1, 1);
        s1 += __shfl_xor_sync(0xffffffffu, s1, 2);
        l0 = l0 * a0 + s0;
        l1 = l1 * a1 + s1;
#pragma unroll
        for (int j = 0; j < 8; j++) {
            o[j][0] *= a0; o[j][1] *= a0;
            o[j][2] *= a1; o[j][3] *= a1;
        }

        // ---- pack P fragments (hi/lo) ----
        uint32_t ph[4][4], pl[4][4];
#pragma unroll
        for (int kt = 0; kt < 4; kt++) {
            const int t0 = 2 * kt, t1 = 2 * kt + 1;
            splitpack(s[t0][0], s[t0][1], ph[kt][0], pl[kt][0]);
            splitpack(s[t0][2], s[t0][3], ph[kt][1], pl[kt][1]);
            splitpack(s[t1][0], s[t1][1], ph[kt][2], pl[kt][2]);
            splitpack(s[t1][2], s[t1][3], ph[kt][3], pl[kt][3]);
        }

        // ---- O += P @ V (3-pass hi/lo), V via ldmatrix.trans ----
#pragma unroll
        for (int kt = 0; kt < 4; kt++) {
#pragma unroll
            for (int dp = 0; dp < 4; dp++) {
                const int kvr = kt * 16 + (lane & 15);
                const uint32_t ob = kvr * 128 + (dp * 2 + (lane >> 4)) * 16;
                uint32_t v_h[4], v_l[4];
                ldsm4t(v_h, kvb + 16384 + swz(ob));
                ldsm4t(v_l, kvb + 24576 + swz(ob));
                mma16816(o[2 * dp],     ph[kt], v_h[0], v_h[1]);
                mma16816(o[2 * dp + 1], ph[kt], v_h[2], v_h[3]);
                mma16816(o[2 * dp],     ph[kt], v_l[0], v_l[1]);
                mma16816(o[2 * dp + 1], ph[kt], v_l[2], v_l[3]);
                mma16816(o[2 * dp],     pl[kt], v_h[0], v_h[1]);
                mma16816(o[2 * dp + 1], pl[kt], v_h[2], v_h[3]);
            }
        }
    }

    // ---- normalize + hi/lo split -> g_aoh/g_aol ----
    const float li0 = 1.0f / l0, li1 = 1.0f / l1;
    const int n0 = q0 + w * 16 + (lane >> 2);
    const size_t ro0 = (size_t)(b * N_ + n0) * C_ + h * D_;
    const size_t ro1 = ro0 + (size_t)8 * C_;
#pragma unroll
    for (int j = 0; j < 8; j++) {
        const int col = j * 8 + ((lane & 3) << 1);
        uint32_t Hw, Lw;
        splitpack(o[j][0] * li0, o[j][1] * li0, Hw, Lw);
        *(uint32_t*)(g_aoh + ro0 + col) = Hw;
        *(uint32_t*)(g_aol + ro0 + col) = Lw;
        splitpack(o[j][2] * li1, o[j][3] * li1, Hw, Lw);
        *(uint32_t*)(g_aoh + ro1 + col) = Hw;
        *(uint32_t*)(g_aol + ro1 + col) = Lw;
    }
}

// ---------------------------------------------------------------------------
extern "C" void kernel_launch(void* const* d_in, const int* in_sizes, int n_in,
                              void* d_out, int out_size)
{
    const float* x      = (const float*)d_in[0];
    const float* w_qkv  = (const float*)d_in[1];
    const float* w_proj = (const float*)d_in[2];
    const float* b_proj = (const float*)d_in[3];
    const int*   kpm    = (const int*)d_in[4];
    float* out = (float*)d_out;

    float* qkv;
    __nv_bfloat16 *xh, *xl, *wqh, *wql, *wph, *wpl, *aoh, *aol;
    int *slotp, *invp, *cntp;
    cudaGetSymbolAddress((void**)&qkv, g_qkv);
    cudaGetSymbolAddress((void**)&xh,  g_xh);
    cudaGetSymbolAddress((void**)&xl,  g_xl);
    cudaGetSymbolAddress((void**)&wqh, g_wqh);
    cudaGetSymbolAddress((void**)&wql, g_wql);
    cudaGetSymbolAddress((void**)&wph, g_wph);
    cudaGetSymbolAddress((void**)&wpl, g_wpl);
    cudaGetSymbolAddress((void**)&aoh, g_aoh);
    cudaGetSymbolAddress((void**)&aol, g_aol);
    cudaGetSymbolAddress((void**)&slotp, g_slot);
    cudaGetSymbolAddress((void**)&invp,  g_inv);
    cudaGetSymbolAddress((void**)&cntp,  g_kvcnt);

    float* qkv_q  = qkv;                          // [M][1024]
    float* qkv_kv = qkv + (size_t)M_ * C_;        // [M][2048]

    // 0) key compaction scan + fp32 -> bf16 hi/lo splits
    compact_scan<<<B_, 256>>>(kpm);
    cvt_hilo<<<(M_ * C_ / 4 + 255) / 256, 256>>>(
        (const float4*)x, (uint2*)xh, (uint2*)xl, M_ * C_ / 4);
    cvt_hilo<<<(QKVN * C_ / 4 + 255) / 256, 256>>>(
        (const float4*)w_qkv, (uint2*)wqh, (uint2*)wql, QKVN * C_ / 4);
    cvt_hilo<<<(C_ * C_ / 4 + 255) / 256, 256>>>(
        (const float4*)w_proj, (uint2*)wph, (uint2*)wpl, C_ * C_ / 4);

    cudaFuncSetAttribute(gemm_mma, cudaFuncAttributeMaxDynamicSharedMemorySize, G_SMEM);

    // 1a) Q gemm: all rows x 1024 cols
    gemm_mma<<<dim3(C_ / 128, M_ / 128), 512, G_SMEM>>>(
        xh, xl, wqh, wql, nullptr, qkv_q, C_, nullptr, nullptr);
    // 1b) KV gemm: compacted rows x 2048 cols (w rows 1024..3071)
    gemm_mma<<<dim3(2048 / 128, M_ / 128), 512, G_SMEM>>>(
        xh, xl, wqh + (size_t)C_ * C_, wql + (size_t)C_ * C_,
        nullptr, qkv_kv, 2048, invp, cntp);

    // 2) RoPE
    rope_q<<<M_, 512>>>();
    rope_kv<<<M_, 512>>>();

    // 3) flash attention over compacted keys
    cudaFuncSetAttribute(flash_attn_mma, cudaFuncAttributeMaxDynamicSharedMemorySize,
                         AT_SMEM);
    flash_attn_mma<<<dim3(N_ / 128, H_, B_), 256, AT_SMEM>>>();

    // 4) out = ao @ w_proj^T + b_proj
    gemm_mma<<<dim3(C_ / 128, M_ / 128), 512, G_SMEM>>>(
        aoh, aol, wph, wpl, b_proj, out, C_, nullptr, nullptr);
}

// round 16
// speedup vs baseline: 1.5497x; 1.0140x over previous
#include <cuda_runtime.h>
#include <cuda_bf16.h>
#include <math.h>
#include <stdint.h>

#define B_   2
#define N_   2048
#define C_   1024
#define H_   16
#define D_   64
#define M_   (B_ * N_)      // 4096
#define QKVN 3072

// ---------------- mma.sync / ldmatrix helpers (portable PTX) ----------------
__device__ __forceinline__ uint32_t smem_u32(const void* p) {
    uint32_t a;
    asm("{ .reg .u64 t; cvta.to.shared.u64 t, %1; cvt.u32.u64 %0, t; }"
        : "=r"(a) : "l"(p));
    return a;
}
__device__ __forceinline__ uint32_t swz(uint32_t off) {  // SW128: bits[6:4] ^= bits[9:7]
    return off ^ ((off >> 3) & 0x70);
}
__device__ __forceinline__ void ldsm4(uint32_t* r, uint32_t addr) {
    asm volatile("ldmatrix.sync.aligned.m8n8.x4.shared.b16 {%0,%1,%2,%3}, [%4];"
                 : "=r"(r[0]), "=r"(r[1]), "=r"(r[2]), "=r"(r[3]) : "r"(addr));
}
__device__ __forceinline__ void ldsm4t(uint32_t* r, uint32_t addr) {
    asm volatile("ldmatrix.sync.aligned.m8n8.x4.trans.shared.b16 {%0,%1,%2,%3}, [%4];"
                 : "=r"(r[0]), "=r"(r[1]), "=r"(r[2]), "=r"(r[3]) : "r"(addr));
}
__device__ __forceinline__ void mma16816(float* d, const uint32_t* a,
                                         uint32_t b0, uint32_t b1) {
    asm volatile(
        "mma.sync.aligned.m16n8k16.row.col.f32.bf16.bf16.f32 "
        "{%0,%1,%2,%3}, {%4,%5,%6,%7}, {%8,%9}, {%0,%1,%2,%3};"
        : "+f"(d[0]), "+f"(d[1]), "+f"(d[2]), "+f"(d[3])
        : "r"(a[0]), "r"(a[1]), "r"(a[2]), "r"(a[3]), "r"(b0), "r"(b1));
}
__device__ __forceinline__ void cp16(uint32_t sdst, const void* gsrc) {
    asm volatile("cp.async.cg.shared.global [%0], [%1], 16;"
                 :: "r"(sdst), "l"(gsrc) : "memory");
}
#define CP_COMMIT() asm volatile("cp.async.commit_group;" ::: "memory")
#define CP_WAIT(n)  asm volatile("cp.async.wait_group %0;" :: "n"(n) : "memory")

// split two floats into packed (hi, lo) bf16x2 words
__device__ __forceinline__ void splitpack(float x, float y, uint32_t& Hw, uint32_t& Lw) {
    __nv_bfloat16 hx = __float2bfloat16(x), hy = __float2bfloat16(y);
    __nv_bfloat16 lx = __float2bfloat16(x - __bfloat162float(hx));
    __nv_bfloat16 ly = __float2bfloat16(y - __bfloat162float(hy));
    Hw = (uint32_t)__bfloat16_as_ushort(hx) | ((uint32_t)__bfloat16_as_ushort(hy) << 16);
    Lw = (uint32_t)__bfloat16_as_ushort(lx) | ((uint32_t)__bfloat16_as_ushort(ly) << 16);
}

// ---------------- scratch ----------------------------------------------------
// g_qkv partition: [0 .. M*C) = Q gemm out; [M*C .. M*3C) = KV gemm out.
__device__ float g_qkv[(size_t)M_ * QKVN];                  // 48 MB
__device__ __nv_bfloat16 g_xh[(size_t)M_ * C_];
__device__ __nv_bfloat16 g_xl[(size_t)M_ * C_];
__device__ __nv_bfloat16 g_wqh[(size_t)QKVN * C_];
__device__ __nv_bfloat16 g_wql[(size_t)QKVN * C_];
__device__ __nv_bfloat16 g_wph[(size_t)C_ * C_];
__device__ __nv_bfloat16 g_wpl[(size_t)C_ * C_];
__device__ __nv_bfloat16 g_qh[(size_t)B_ * H_ * N_ * D_];
__device__ __nv_bfloat16 g_ql[(size_t)B_ * H_ * N_ * D_];
__device__ __nv_bfloat16 g_kh[(size_t)B_ * H_ * N_ * D_];   // compacted keys
__device__ __nv_bfloat16 g_kl[(size_t)B_ * H_ * N_ * D_];
__device__ __nv_bfloat16 g_vh[(size_t)B_ * H_ * N_ * D_];
__device__ __nv_bfloat16 g_vl[(size_t)B_ * H_ * N_ * D_];
__device__ __nv_bfloat16 g_aoh[(size_t)M_ * C_];
__device__ __nv_bfloat16 g_aol[(size_t)M_ * C_];
__device__ int g_slot[M_];            // compact slot per (b,n), -1 if masked
__device__ int g_inv[M_];             // absolute token row per (b, slot); pad -> b*N_
__device__ int g_kvcnt[B_];           // valid-key count per batch

extern __shared__ __align__(1024) char dyn_sm[];

// ---------------- fused fp32 -> (hi, lo) bf16 split (3 segments) -------------
#define CVT_N1 (M_ * C_ / 4)            // x        : 1048576
#define CVT_N2 (QKVN * C_ / 4)          // w_qkv    :  786432
#define CVT_N3 (C_ * C_ / 4)            // w_proj   :  262144
#define CVT_TOT (CVT_N1 + CVT_N2 + CVT_N3)

__global__ void __launch_bounds__(256) cvt_hilo3(
    const float4* __restrict__ s1, uint2* __restrict__ h1, uint2* __restrict__ l1,
    const float4* __restrict__ s2, uint2* __restrict__ h2, uint2* __restrict__ l2,
    const float4* __restrict__ s3, uint2* __restrict__ h3, uint2* __restrict__ l3)
{
    int i = blockIdx.x * 256 + threadIdx.x;
    if (i >= CVT_TOT) return;
    const float4* src; uint2 *hi, *lo; int j;
    if (i < CVT_N1)                { src = s1; hi = h1; lo = l1; j = i; }
    else if (i < CVT_N1 + CVT_N2)  { src = s2; hi = h2; lo = l2; j = i - CVT_N1; }
    else                           { src = s3; hi = h3; lo = l3; j = i - CVT_N1 - CVT_N2; }
    float4 v = src[j];
    uint2 Hv, Lv;
    splitpack(v.x, v.y, Hv.x, Lv.x);
    splitpack(v.z, v.w, Hv.y, Lv.y);
    hi[j] = Hv;
    lo[j] = Lv;
}

// ---------------- deterministic key compaction scan -------------------------
__global__ void __launch_bounds__(256) compact_scan(const int* __restrict__ kpm)
{
    __shared__ int ps[256];
    const int b = blockIdx.x, t = threadIdx.x;
    int v[8], s = 0;
#pragma unroll
    for (int i = 0; i < 8; i++) {
        v[i] = (kpm[b * N_ + t * 8 + i] != 0);
        s += v[i];
        g_inv[b * N_ + t * 8 + i] = b * N_;    // pad default (in-bounds row)
    }
    ps[t] = s;
    __syncthreads();
    for (int off = 1; off < 256; off <<= 1) {
        int x = (t >= off) ? ps[t - off] : 0;
        __syncthreads();
        ps[t] += x;
        __syncthreads();
    }
    int base = ps[t] - s;   // exclusive prefix
#pragma unroll
    for (int i = 0; i < 8; i++) {
        const int n = t * 8 + i;
        g_slot[b * N_ + n] = v[i] ? base : -1;
        if (v[i]) g_inv[b * N_ + base] = b * N_ + n;
        base += v[i];
    }
    if (t == 255) g_kvcnt[b] = ps[255];
}

// ---------------- GEMM body: C = A @ B^T (+bias), bf16 hi/lo 3-pass ---------
// 512 threads, 16 warps, warp tile 32x32, block tile 128x128, cp.async 4-stage.
#define G_STAGE 32768
#define G_SMEM  (4 * G_STAGE)          // 131072

__device__ __forceinline__ void gemm_body(
    const __nv_bfloat16* __restrict__ Ah, const __nv_bfloat16* __restrict__ Al,
    const __nv_bfloat16* __restrict__ Bh, const __nv_bfloat16* __restrict__ Bl,
    const float* __restrict__ bias, float* __restrict__ C, int Nn, int bn,
    const int* __restrict__ rowmap)
{
    const int tid = threadIdx.x, lane = tid & 31, w = tid >> 5;
    const int wm = w >> 2, wn = w & 3;
    const int bm = blockIdx.y << 7;
    const uint32_t sb = smem_u32(dyn_sm);

    float acc[2][4][4];
#pragma unroll
    for (int mt = 0; mt < 2; mt++)
#pragma unroll
        for (int j = 0; j < 4; j++)
#pragma unroll
            for (int q = 0; q < 4; q++) acc[mt][j][q] = 0.0f;

    uint32_t offA[2], offB[2];
#pragma unroll
    for (int mt = 0; mt < 2; mt++) {
        const int rowA = wm * 32 + mt * 16 + (lane & 15);
        offA[mt] = rowA * 64 + (lane >> 4) * 16;
    }
#pragma unroll
    for (int np = 0; np < 2; np++) {
        const int nB = wn * 32 + np * 16 + (lane & 7) + ((lane >> 4) << 3);
        offB[np] = nB * 64 + ((lane >> 3) & 1) * 16;
    }

    const __nv_bfloat16* srcs[4] = {Ah, Al, Bh, Bl};
    const __nv_bfloat16* gsrc[4];
    uint32_t sdst[4];
#pragma unroll
    for (int i = 0; i < 4; i++) {
        const int gid = tid + i * 512;
        const int op = gid >> 9, g = gid & 511;
        const int row = g >> 2, kg = g & 3;
        int arow;
        if (op < 2) arow = rowmap ? rowmap[bm + row] : (bm + row);
        else        arow = bn + row;
        gsrc[i] = srcs[op] + (size_t)arow * C_ + kg * 8;
        sdst[i] = op * 8192 + swz(row * 64 + kg * 16);
    }

    auto issue = [&](int c) {
        const uint32_t stb = sb + (c & 3) * G_STAGE;
#pragma unroll
        for (int i = 0; i < 4; i++)
            cp16(stb + sdst[i], gsrc[i] + c * 32);
    };

    issue(0); CP_COMMIT();
    issue(1); CP_COMMIT();
    issue(2); CP_COMMIT();

    for (int c = 0; c < 32; c++) {
        CP_WAIT(2);
        __syncthreads();
        if (c + 3 < 32) issue(c + 3);
        CP_COMMIT();

        const uint32_t stb = sb + (c & 3) * G_STAGE;
#pragma unroll
        for (int ks = 0; ks < 2; ks++) {
            uint32_t a_h[2][4], a_l[2][4];
#pragma unroll
            for (int mt = 0; mt < 2; mt++) {
                ldsm4(a_h[mt], stb + swz(offA[mt] + ks * 32));
                ldsm4(a_l[mt], stb + 8192 + swz(offA[mt] + ks * 32));
            }
#pragma unroll
            for (int np = 0; np < 2; np++) {
                uint32_t b_h[4], b_l[4];
                ldsm4(b_h, stb + 16384 + swz(offB[np] + ks * 32));
                ldsm4(b_l, stb + 24576 + swz(offB[np] + ks * 32));
#pragma unroll
                for (int mt = 0; mt < 2; mt++) {
                    mma16816(acc[mt][2 * np],     a_h[mt], b_h[0], b_h[1]);
                    mma16816(acc[mt][2 * np + 1], a_h[mt], b_h[2], b_h[3]);
                    mma16816(acc[mt][2 * np],     a_h[mt], b_l[0], b_l[1]);
                    mma16816(acc[mt][2 * np + 1], a_h[mt], b_l[2], b_l[3]);
                    mma16816(acc[mt][2 * np],     a_l[mt], b_h[0], b_h[1]);
                    mma16816(acc[mt][2 * np + 1], a_l[mt], b_h[2], b_h[3]);
                }
            }
        }
    }

#pragma unroll
    for (int mt = 0; mt < 2; mt++)
#pragma unroll
        for (int j = 0; j < 4; j++) {
            const int row = bm + wm * 32 + mt * 16 + (lane >> 2);
            const int col = bn + wn * 32 + j * 8 + ((lane & 3) << 1);
            const float b0 = bias ? bias[col] : 0.0f;
            const float b1 = bias ? bias[col + 1] : 0.0f;
            float2 v0 = make_float2(acc[mt][j][0] + b0, acc[mt][j][1] + b1);
            float2 v1 = make_float2(acc[mt][j][2] + b0, acc[mt][j][3] + b1);
            *(float2*)(C + (size_t)row * Nn + col) = v0;
            *(float2*)(C + (size_t)(row + 8) * Nn + col) = v1;
        }
}

// merged QKV GEMM: bx<8 -> Q (all rows); bx>=8 -> KV (compacted rows)
__global__ void __launch_bounds__(512, 1) gemm_qkv(
    const __nv_bfloat16* __restrict__ xh, const __nv_bfloat16* __restrict__ xl,
    const __nv_bfloat16* __restrict__ wqh, const __nv_bfloat16* __restrict__ wql,
    float* __restrict__ q_out, float* __restrict__ kv_out,
    const int* __restrict__ rowmap, const int* __restrict__ cnts)
{
    const int bx = blockIdx.x;
    if (bx < 8) {
        gemm_body(xh, xl, wqh, wql, nullptr, q_out, C_, bx << 7, nullptr);
    } else {
        const int bm = blockIdx.y << 7;
        if ((bm & (N_ - 1)) >= cnts[bm >> 11]) return;
        gemm_body(xh, xl, wqh + (size_t)C_ * C_, wql + (size_t)C_ * C_,
                  nullptr, kv_out, 2048, (bx - 8) << 7, rowmap);
    }
}

// plain GEMM (projection)
__global__ void __launch_bounds__(512, 1) gemm_std(
    const __nv_bfloat16* __restrict__ Ah, const __nv_bfloat16* __restrict__ Al,
    const __nv_bfloat16* __restrict__ Bh, const __nv_bfloat16* __restrict__ Bl,
    const float* __restrict__ bias, float* __restrict__ C, int Nn)
{
    gemm_body(Ah, Al, Bh, Bl, bias, C, Nn, blockIdx.x << 7, nullptr);
}

// ---------------- fused RoPE: blocks [0,M) = Q, [M,2M) = KV ------------------
__global__ void __launch_bounds__(512) rope_all()
{
    const int h = threadIdx.x >> 5;
    const int i = threadIdx.x & 31;
    float inv = exp2f(-11.0f * (float)i * (1.0f / 32.0f));  // 2048^(-i/32)

    if (blockIdx.x < M_) {
        // ---- Q path ----
        const int m = blockIdx.x;
        const int b = m >> 11, n = m & (N_ - 1);
        const float* row = g_qkv + (size_t)m * C_;           // Q section
        float q0 = row[h * D_ + i], q1 = row[h * D_ + i + 32];
        float th = (float)n * inv;
        float cs = cosf(th), sn = sinf(th);
        float qa = q0 * cs - q1 * sn, qb = q1 * cs + q0 * sn;

        size_t base = (((size_t)b * H_ + h) * N_ + n) * D_;
        __nv_bfloat16 hv;
        hv = __float2bfloat16(qa);
        g_qh[base + i] = hv;
        g_ql[base + i] = __float2bfloat16(qa - __bfloat162float(hv));
        hv = __float2bfloat16(qb);
        g_qh[base + i + 32] = hv;
        g_ql[base + i + 32] = __float2bfloat16(qb - __bfloat162float(hv));
    } else {
        // ---- KV path (compacted rows) ----
        const int m = blockIdx.x - M_;            // b * N_ + slot
        const int b = m >> 11, slot = m & (N_ - 1);
        if (slot >= g_kvcnt[b]) return;
        const int n = g_inv[m] & (N_ - 1);        // original token position
        const float* row = g_qkv + (size_t)M_ * C_ + (size_t)m * 2048;
        float k0 = row[h * D_ + i],        k1 = row[h * D_ + i + 32];
        float v0 = row[C_ + h * D_ + i],   v1 = row[C_ + h * D_ + i + 32];
        float th = (float)n * inv;
        float cs = cosf(th), sn = sinf(th);
        float ka = k0 * cs - k1 * sn, kb = k1 * cs + k0 * sn;

        size_t base = (((size_t)b * H_ + h) * N_ + slot) * D_;
        const float vals[4] = {ka, kb, v0, v1};
        __nv_bfloat16* Hp[4] = {g_kh + base + i, g_kh + base + i + 32,
                                g_vh + base + i, g_vh + base + i + 32};
        __nv_bfloat16* Lp[4] = {g_kl + base + i, g_kl + base + i + 32,
                                g_vl + base + i, g_vl + base + i + 32};
#pragma unroll
        for (int t = 0; t < 4; t++) {
            __nv_bfloat16 hv = __float2bfloat16(vals[t]);
            *Hp[t] = hv;
            *Lp[t] = __float2bfloat16(vals[t] - __bfloat162float(hv));
        }
    }
}

// ---------------- flash attention over COMPACTED keys, BQ=128 BKV=64 --------
#define AT_KV0  32768
#define AT_SMEM (98304 + 512)

__global__ void __launch_bounds__(256, 1) flash_attn_mma()
{
    const int tid = threadIdx.x, lane = tid & 31, w = tid >> 5;
    const int b = blockIdx.z, h = blockIdx.y;
    const int q0 = blockIdx.x << 7;
    const uint32_t sb = smem_u32(dyn_sm);
    const size_t hoff = ((size_t)b * H_ + h) * N_ * D_;
    float* mbuf = (float*)(dyn_sm + 98304);

    const int cnt = g_kvcnt[b];
    int nkv = (cnt + 63) >> 6;
    if (nkv < 1) nkv = 1;

    // stage Q hi/lo [128][64]
    {
        const __nv_bfloat16* qsrc[2] = {g_qh + hoff + (size_t)q0 * D_,
                                        g_ql + hoff + (size_t)q0 * D_};
#pragma unroll
        for (int i = 0; i < 8; i++) {
            const int gid = tid + i * 256;
            const int op = gid >> 10, g = gid & 1023;
            const int row = g >> 3, dg = g & 7;
            uint4 v = *(const uint4*)(qsrc[op] + row * 64 + dg * 8);
            *(uint4*)(dyn_sm + op * 16384 + swz(row * 128 + dg * 16)) = v;
        }
    }

    const __nv_bfloat16* ksrc[4] = {g_kh + hoff, g_kl + hoff, g_vh + hoff, g_vl + hoff};
    const __nv_bfloat16* kgsrc[8];
    uint32_t ksdst[8];
#pragma unroll
    for (int i = 0; i < 8; i++) {
        const int gid = tid + i * 256;
        const int op = gid >> 9, g = gid & 511;
        const int row = g >> 3, dg = g & 7;
        kgsrc[i] = ksrc[op] + (size_t)row * D_ + dg * 8;
        ksdst[i] = AT_KV0 + op * 8192 + swz(row * 128 + dg * 16);
    }
    auto issue_kv = [&](int it) {
        const uint32_t stoff = (it & 1) * 32768;
#pragma unroll
        for (int i = 0; i < 8; i++)
            cp16(sb + stoff + ksdst[i], kgsrc[i] + it * 64 * D_);
        if (tid < 64)
            mbuf[(it & 1) * 64 + tid] = (it * 64 + tid < cnt) ? 0.0f : -1e9f;
    };

    issue_kv(0); CP_COMMIT();
    __syncthreads();

    // preload Q fragments
    uint32_t qfh[4][4], qfl[4][4];
    {
        const int rowQ = w * 16 + (lane & 15);
        const uint32_t base = rowQ * 128 + (lane >> 4) * 16;
#pragma unroll
        for (int ks = 0; ks < 4; ks++) {
            ldsm4(qfh[ks], sb + swz(base + ks * 32));
            ldsm4(qfl[ks], sb + 16384 + swz(base + ks * 32));
        }
    }

    float o[8][4];
#pragma unroll
    for (int j = 0; j < 8; j++)
#pragma unroll
        for (int q = 0; q < 4; q++) o[j][q] = 0.0f;
    float m0 = -INFINITY, m1 = -INFINITY, l0 = 0.0f, l1 = 0.0f;

    for (int it = 0; it < nkv; it++) {
        CP_WAIT(0);
        __syncthreads();
        if (it + 1 < nkv) issue_kv(it + 1);
        CP_COMMIT();

        const uint32_t kvb = sb + AT_KV0 + (it & 1) * 32768;
        const float* mb = mbuf + (it & 1) * 64;

        // ---- S = Q K^T (3-pass hi/lo) ----
        float s[8][4];
#pragma unroll
        for (int j = 0; j < 8; j++)
#pragma unroll
            for (int q = 0; q < 4; q++) s[j][q] = 0.0f;

#pragma unroll
        for (int ks = 0; ks < 4; ks++) {
#pragma unroll
            for (int np = 0; np < 4; np++) {
                const int nB = np * 16 + (lane & 7) + ((lane >> 4) << 3);
                const uint32_t ob = nB * 128 + ((lane >> 3) & 1) * 16 + ks * 32;
                uint32_t kb_h[4], kb_l[4];
                ldsm4(kb_h, kvb + swz(ob));
                ldsm4(kb_l, kvb + 8192 + swz(ob));
                mma16816(s[2 * np],     qfh[ks], kb_h[0], kb_h[1]);
                mma16816(s[2 * np + 1], qfh[ks], kb_h[2], kb_h[3]);
                mma16816(s[2 * np],     qfh[ks], kb_l[0], kb_l[1]);
                mma16816(s[2 * np + 1], qfh[ks], kb_l[2], kb_l[3]);
                mma16816(s[2 * np],     qfl[ks], kb_h[0], kb_h[1]);
                mma16816(s[2 * np + 1], qfl[ks], kb_h[2], kb_h[3]);
            }
        }

        // ---- scale + tail mask + online softmax ----
        const float scale = 0.125f;
        float mx0 = -INFINITY, mx1 = -INFINITY;
#pragma unroll
        for (int j = 0; j < 8; j++) {
            const int col = j * 8 + ((lane & 3) << 1);
            const float mb0 = mb[col], mb1 = mb[col + 1];
            s[j][0] = fmaf(s[j][0], scale, mb0);
            s[j][1] = fmaf(s[j][1], scale, mb1);
            s[j][2] = fmaf(s[j][2], scale, mb0);
            s[j][3] = fmaf(s[j][3], scale, mb1);
            mx0 = fmaxf(mx0, fmaxf(s[j][0], s[j][1]));
            mx1 = fmaxf(mx1, fmaxf(s[j][2], s[j][3]));
        }
        mx0 = fmaxf(mx0, __shfl_xor_sync(0xffffffffu, mx0, 1));
        mx0 = fmaxf(mx0, __shfl_xor_sync(0xffffffffu, mx0, 2));
        mx1 = fmaxf(mx1, __shfl_xor_sync(0xffffffffu, mx1, 1));
        mx1 = fmaxf(mx1, __shfl_xor_sync(0xffffffffu, mx1, 2));
        const float mn0 = fmaxf(m0, mx0), mn1 = fmaxf(m1, mx1);
        const float a0 = __expf(m0 - mn0), a1 = __expf(m1 - mn1);
        m0 = mn0; m1 = mn1;
        float s0 = 0.0f, s1 = 0.0f;
#pragma unroll
        for (int j = 0; j < 8; j++) {
            s[j][0] = __expf(s[j][0] - mn0);
            s[j][1] = __expf(s[j][1] - mn0);
            s[j][2] = __expf(s[j][2] - mn1);
            s[j][3] = __expf(s[j][3] - mn1);
            s0 += s[j][0] + s[j][1];
            s1 += s[j][2] + s[j][3];
        }
        s0 += __shfl_xor_sync(0xffffffffu, s0, 1);
        s0 += __shfl_xor_sync(0xffffffffu, s0, 2);
        s1 += __shfl_xor_sync(0xffffffffu, s1, 1);
        s1 += __shfl_xor_sync(0xffffffffu, s1, 2);
        l0 = l0 * a0 + s0;
        l1 = l1 * a1 + s1;
#pragma unroll
        for (int j = 0; j < 8; j++) {
            o[j][0] *= a0; o[j][1] *= a0;
            o[j][2] *= a1; o[j][3] *= a1;
        }

        // ---- pack P fragments (hi/lo) ----
        uint32_t ph[4][4], pl[4][4];
#pragma unroll
        for (int kt = 0; kt < 4; kt++) {
            const int t0 = 2 * kt, t1 = 2 * kt + 1;
            splitpack(s[t0][0], s[t0][1], ph[kt][0], pl[kt][0]);
            splitpack(s[t0][2], s[t0][3], ph[kt][1], pl[kt][1]);
            splitpack(s[t1][0], s[t1][1], ph[kt][2], pl[kt][2]);
            splitpack(s[t1][2], s[t1][3], ph[kt][3], pl[kt][3]);
        }

        // ---- O += P @ V (3-pass hi/lo), V via ldmatrix.trans ----
#pragma unroll
        for (int kt = 0; kt < 4; kt++) {
#pragma unroll
            for (int dp = 0; dp < 4; dp++) {
                const int kvr = kt * 16 + (lane & 15);
                const uint32_t ob = kvr * 128 + (dp * 2 + (lane >> 4)) * 16;
                uint32_t v_h[4], v_l[4];
                ldsm4t(v_h, kvb + 16384 + swz(ob));
                ldsm4t(v_l, kvb + 24576 + swz(ob));
                mma16816(o[2 * dp],     ph[kt], v_h[0], v_h[1]);
                mma16816(o[2 * dp + 1], ph[kt], v_h[2], v_h[3]);
                mma16816(o[2 * dp],     ph[kt], v_l[0], v_l[1]);
                mma16816(o[2 * dp + 1], ph[kt], v_l[2], v_l[3]);
                mma16816(o[2 * dp],     pl[kt], v_h[0], v_h[1]);
                mma16816(o[2 * dp + 1], pl[kt], v_h[2], v_h[3]);
            }
        }
    }

    // ---- normalize + hi/lo split -> g_aoh/g_aol ----
    const float li0 = 1.0f / l0, li1 = 1.0f / l1;
    const int n0 = q0 + w * 16 + (lane >> 2);
    const size_t ro0 = (size_t)(b * N_ + n0) * C_ + h * D_;
    const size_t ro1 = ro0 + (size_t)8 * C_;
#pragma unroll
    for (int j = 0; j < 8; j++) {
        const int col = j * 8 + ((lane & 3) << 1);
        uint32_t Hw, Lw;
        splitpack(o[j][0] * li0, o[j][1] * li0, Hw, Lw);
        *(uint32_t*)(g_aoh + ro0 + col) = Hw;
        *(uint32_t*)(g_aol + ro0 + col) = Lw;
        splitpack(o[j][2] * li1, o[j][3] * li1, Hw, Lw);
        *(uint32_t*)(g_aoh + ro1 + col) = Hw;
        *(uint32_t*)(g_aol + ro1 + col) = Lw;
    }
}

// ---------------------------------------------------------------------------
extern "C" void kernel_launch(void* const* d_in, const int* in_sizes, int n_in,
                              void* d_out, int out_size)
{
    const float* x      = (const float*)d_in[0];
    const float* w_qkv  = (const float*)d_in[1];
    const float* w_proj = (const float*)d_in[2];
    const float* b_proj = (const float*)d_in[3];
    const int*   kpm    = (const int*)d_in[4];
    float* out = (float*)d_out;

    float* qkv;
    __nv_bfloat16 *xh, *xl, *wqh, *wql, *wph, *wpl, *aoh, *aol;
    int *invp, *cntp;
    cudaGetSymbolAddress((void**)&qkv, g_qkv);
    cudaGetSymbolAddress((void**)&xh,  g_xh);
    cudaGetSymbolAddress((void**)&xl,  g_xl);
    cudaGetSymbolAddress((void**)&wqh, g_wqh);
    cudaGetSymbolAddress((void**)&wql, g_wql);
    cudaGetSymbolAddress((void**)&wph, g_wph);
    cudaGetSymbolAddress((void**)&wpl, g_wpl);
    cudaGetSymbolAddress((void**)&aoh, g_aoh);
    cudaGetSymbolAddress((void**)&aol, g_aol);
    cudaGetSymbolAddress((void**)&invp,  g_inv);
    cudaGetSymbolAddress((void**)&cntp,  g_kvcnt);

    float* qkv_q  = qkv;                          // [M][1024]
    float* qkv_kv = qkv + (size_t)M_ * C_;        // [M][2048]

    // 0) key compaction scan + fused fp32 -> bf16 hi/lo split
    compact_scan<<<B_, 256>>>(kpm);
    cvt_hilo3<<<(CVT_TOT + 255) / 256, 256>>>(
        (const float4*)x,      (uint2*)xh,  (uint2*)xl,
        (const float4*)w_qkv,  (uint2*)wqh, (uint2*)wql,
        (const float4*)w_proj, (uint2*)wph, (uint2*)wpl);

    cudaFuncSetAttribute(gemm_qkv, cudaFuncAttributeMaxDynamicSharedMemorySize, G_SMEM);
    cudaFuncSetAttribute(gemm_std, cudaFuncAttributeMaxDynamicSharedMemorySize, G_SMEM);

    // 1) merged Q + KV gemm (Q: cols 0-1023 all rows; KV: cols 1024-3071 compacted)
    gemm_qkv<<<dim3(24, M_ / 128), 512, G_SMEM>>>(
        xh, xl, wqh, wql, qkv_q, qkv_kv, invp, cntp);

    // 2) fused RoPE (Q + compacted KV)
    rope_all<<<2 * M_, 512>>>();

    // 3) flash attention over compacted keys
    cudaFuncSetAttribute(flash_attn_mma, cudaFuncAttributeMaxDynamicSharedMemorySize,
                         AT_SMEM);
    flash_attn_mma<<<dim3(N_ / 128, H_, B_), 256, AT_SMEM>>>();

    // 4) out = ao @ w_proj^T + b_proj
    gemm_std<<<dim3(C_ / 128, M_ / 128), 512, G_SMEM>>>(
        aoh, aol, wph, wpl, b_proj, out, C_);
}

// round 17
// speedup vs baseline: 2.1066x; 1.3594x over previous
#include <cuda_runtime.h>
#include <cuda_fp16.h>
#include <math.h>
#include <stdint.h>

#define B_   2
#define N_   2048
#define C_   1024
#define H_   16
#define D_   64
#define M_   (B_ * N_)      // 4096
#define QKVN 3072

// ---------------- mma.sync / ldmatrix helpers (portable PTX) ----------------
__device__ __forceinline__ uint32_t smem_u32(const void* p) {
    uint32_t a;
    asm("{ .reg .u64 t; cvta.to.shared.u64 t, %1; cvt.u32.u64 %0, t; }"
        : "=r"(a) : "l"(p));
    return a;
}
__device__ __forceinline__ uint32_t swz(uint32_t off) {  // SW128: bits[6:4] ^= bits[9:7]
    return off ^ ((off >> 3) & 0x70);
}
__device__ __forceinline__ void ldsm4(uint32_t* r, uint32_t addr) {
    asm volatile("ldmatrix.sync.aligned.m8n8.x4.shared.b16 {%0,%1,%2,%3}, [%4];"
                 : "=r"(r[0]), "=r"(r[1]), "=r"(r[2]), "=r"(r[3]) : "r"(addr));
}
__device__ __forceinline__ void ldsm4t(uint32_t* r, uint32_t addr) {
    asm volatile("ldmatrix.sync.aligned.m8n8.x4.trans.shared.b16 {%0,%1,%2,%3}, [%4];"
                 : "=r"(r[0]), "=r"(r[1]), "=r"(r[2]), "=r"(r[3]) : "r"(addr));
}
__device__ __forceinline__ void mma16816(float* d, const uint32_t* a,
                                         uint32_t b0, uint32_t b1) {
    asm volatile(
        "mma.sync.aligned.m16n8k16.row.col.f32.f16.f16.f32 "
        "{%0,%1,%2,%3}, {%4,%5,%6,%7}, {%8,%9}, {%0,%1,%2,%3};"
        : "+f"(d[0]), "+f"(d[1]), "+f"(d[2]), "+f"(d[3])
        : "r"(a[0]), "r"(a[1]), "r"(a[2]), "r"(a[3]), "r"(b0), "r"(b1));
}
__device__ __forceinline__ void cp16(uint32_t sdst, const void* gsrc) {
    asm volatile("cp.async.cg.shared.global [%0], [%1], 16;"
                 :: "r"(sdst), "l"(gsrc) : "memory");
}
#define CP_COMMIT() asm volatile("cp.async.commit_group;" ::: "memory")
#define CP_WAIT(n)  asm volatile("cp.async.wait_group %0;" :: "n"(n) : "memory")

// fp16 pack helpers
__device__ __forceinline__ uint32_t pack2h(float x, float y) {
    __half hx = __float2half_rn(x), hy = __float2half_rn(y);
    return (uint32_t)__half_as_ushort(hx) | ((uint32_t)__half_as_ushort(hy) << 16);
}
__device__ __forceinline__ void split2h(float x, float y, uint32_t& Hw, uint32_t& Lw) {
    __half hx = __float2half_rn(x), hy = __float2half_rn(y);
    __half lx = __float2half_rn(x - __half2float(hx));
    __half ly = __float2half_rn(y - __half2float(hy));
    Hw = (uint32_t)__half_as_ushort(hx) | ((uint32_t)__half_as_ushort(hy) << 16);
    Lw = (uint32_t)__half_as_ushort(lx) | ((uint32_t)__half_as_ushort(ly) << 16);
}

// ---------------- scratch ----------------------------------------------------
// g_qkv partition: [0 .. M*C) = Q gemm out; [M*C .. M*3C) = KV gemm out.
__device__ float g_qkv[(size_t)M_ * QKVN];                  // 48 MB
__device__ __half g_xh[(size_t)M_ * C_];                    // x rounded (A side)
__device__ __half g_wqh[(size_t)QKVN * C_];                 // w_qkv hi/lo (B side)
__device__ __half g_wql[(size_t)QKVN * C_];
__device__ __half g_wph[(size_t)C_ * C_];                   // w_proj hi/lo
__device__ __half g_wpl[(size_t)C_ * C_];
__device__ __half g_qh[(size_t)B_ * H_ * N_ * D_];          // Q rounded
__device__ __half g_kh[(size_t)B_ * H_ * N_ * D_];          // K hi/lo, compacted
__device__ __half g_kl[(size_t)B_ * H_ * N_ * D_];
__device__ __half g_vh[(size_t)B_ * H_ * N_ * D_];          // V hi/lo, compacted
__device__ __half g_vl[(size_t)B_ * H_ * N_ * D_];
__device__ __half g_aoh[(size_t)M_ * C_];                   // attn out rounded
__device__ int g_slot[M_];
__device__ int g_inv[M_];
__device__ int g_kvcnt[B_];

extern __shared__ __align__(1024) char dyn_sm[];

// ---------------- fused fp32 -> fp16 conversion (3 segments) -----------------
// x: round only; w_qkv, w_proj: hi/lo split.
#define CVT_N1 (M_ * C_ / 4)
#define CVT_N2 (QKVN * C_ / 4)
#define CVT_N3 (C_ * C_ / 4)
#define CVT_TOT (CVT_N1 + CVT_N2 + CVT_N3)

__global__ void __launch_bounds__(256) cvt_fp16(
    const float4* __restrict__ s1, uint2* __restrict__ h1,
    const float4* __restrict__ s2, uint2* __restrict__ h2, uint2* __restrict__ l2,
    const float4* __restrict__ s3, uint2* __restrict__ h3, uint2* __restrict__ l3)
{
    int i = blockIdx.x * 256 + threadIdx.x;
    if (i >= CVT_TOT) return;
    if (i < CVT_N1) {
        float4 v = s1[i];
        uint2 Hv;
        Hv.x = pack2h(v.x, v.y);
        Hv.y = pack2h(v.z, v.w);
        h1[i] = Hv;
    } else {
        const float4* src; uint2 *hi, *lo; int j;
        if (i < CVT_N1 + CVT_N2) { src = s2; hi = h2; lo = l2; j = i - CVT_N1; }
        else                     { src = s3; hi = h3; lo = l3; j = i - CVT_N1 - CVT_N2; }
        float4 v = src[j];
        uint2 Hv, Lv;
        split2h(v.x, v.y, Hv.x, Lv.x);
        split2h(v.z, v.w, Hv.y, Lv.y);
        hi[j] = Hv;
        lo[j] = Lv;
    }
}

// ---------------- deterministic key compaction scan -------------------------
__global__ void __launch_bounds__(256) compact_scan(const int* __restrict__ kpm)
{
    __shared__ int ps[256];
    const int b = blockIdx.x, t = threadIdx.x;
    int v[8], s = 0;
#pragma unroll
    for (int i = 0; i < 8; i++) {
        v[i] = (kpm[b * N_ + t * 8 + i] != 0);
        s += v[i];
        g_inv[b * N_ + t * 8 + i] = b * N_;
    }
    ps[t] = s;
    __syncthreads();
    for (int off = 1; off < 256; off <<= 1) {
        int x = (t >= off) ? ps[t - off] : 0;
        __syncthreads();
        ps[t] += x;
        __syncthreads();
    }
    int base = ps[t] - s;
#pragma unroll
    for (int i = 0; i < 8; i++) {
        const int n = t * 8 + i;
        g_slot[b * N_ + n] = v[i] ? base : -1;
        if (v[i]) g_inv[b * N_ + base] = b * N_ + n;
        base += v[i];
    }
    if (t == 255) g_kvcnt[b] = ps[255];
}

// ---------------- GEMM body: C = A @ (Bh+Bl)^T (+bias), fp16 2-pass ---------
// 512 threads, 16 warps, warp tile 32x32, block tile 128x128, cp.async 4-stage.
// Stage = 3 ops x 8KB = 24KB.
#define G_STAGE 24576
#define G_SMEM  (4 * G_STAGE)          // 98304

__device__ __forceinline__ void gemm_body(
    const __half* __restrict__ A,
    const __half* __restrict__ Bh, const __half* __restrict__ Bl,
    const float* __restrict__ bias, float* __restrict__ C, int Nn, int bn,
    const int* __restrict__ rowmap)
{
    const int tid = threadIdx.x, lane = tid & 31, w = tid >> 5;
    const int wm = w >> 2, wn = w & 3;
    const int bm = blockIdx.y << 7;
    const uint32_t sb = smem_u32(dyn_sm);

    float acc[2][4][4];
#pragma unroll
    for (int mt = 0; mt < 2; mt++)
#pragma unroll
        for (int j = 0; j < 4; j++)
#pragma unroll
            for (int q = 0; q < 4; q++) acc[mt][j][q] = 0.0f;

    uint32_t offA[2], offB[2];
#pragma unroll
    for (int mt = 0; mt < 2; mt++) {
        const int rowA = wm * 32 + mt * 16 + (lane & 15);
        offA[mt] = rowA * 64 + (lane >> 4) * 16;
    }
#pragma unroll
    for (int np = 0; np < 2; np++) {
        const int nB = wn * 32 + np * 16 + (lane & 7) + ((lane >> 4) << 3);
        offB[np] = nB * 64 + ((lane >> 3) & 1) * 16;
    }

    // cp.async: 1536 granules of 16B per stage -> 3 per thread
    const __half* srcs[3] = {A, Bh, Bl};
    const __half* gsrc[3];
    uint32_t sdst[3];
#pragma unroll
    for (int i = 0; i < 3; i++) {
        const int gid = tid + i * 512;
        const int op = gid >> 9, g = gid & 511;
        const int row = g >> 2, kg = g & 3;
        int arow;
        if (op == 0) arow = rowmap ? rowmap[bm + row] : (bm + row);
        else         arow = bn + row;
        gsrc[i] = srcs[op] + (size_t)arow * C_ + kg * 8;
        sdst[i] = op * 8192 + swz(row * 64 + kg * 16);
    }

    auto issue = [&](int c) {
        const uint32_t stb = sb + (c & 3) * G_STAGE;
#pragma unroll
        for (int i = 0; i < 3; i++)
            cp16(stb + sdst[i], gsrc[i] + c * 32);
    };

    issue(0); CP_COMMIT();
    issue(1); CP_COMMIT();
    issue(2); CP_COMMIT();

    for (int c = 0; c < 32; c++) {
        CP_WAIT(2);
        __syncthreads();
        if (c + 3 < 32) issue(c + 3);
        CP_COMMIT();

        const uint32_t stb = sb + (c & 3) * G_STAGE;
#pragma unroll
        for (int ks = 0; ks < 2; ks++) {
            uint32_t a[2][4];
#pragma unroll
            for (int mt = 0; mt < 2; mt++)
                ldsm4(a[mt], stb + swz(offA[mt] + ks * 32));
#pragma unroll
            for (int np = 0; np < 2; np++) {
                uint32_t b_h[4], b_l[4];
                ldsm4(b_h, stb + 8192  + swz(offB[np] + ks * 32));
                ldsm4(b_l, stb + 16384 + swz(offB[np] + ks * 32));
#pragma unroll
                for (int mt = 0; mt < 2; mt++) {
                    mma16816(acc[mt][2 * np],     a[mt], b_h[0], b_h[1]);
                    mma16816(acc[mt][2 * np + 1], a[mt], b_h[2], b_h[3]);
                    mma16816(acc[mt][2 * np],     a[mt], b_l[0], b_l[1]);
                    mma16816(acc[mt][2 * np + 1], a[mt], b_l[2], b_l[3]);
                }
            }
        }
    }

#pragma unroll
    for (int mt = 0; mt < 2; mt++)
#pragma unroll
        for (int j = 0; j < 4; j++) {
            const int row = bm + wm * 32 + mt * 16 + (lane >> 2);
            const int col = bn + wn * 32 + j * 8 + ((lane & 3) << 1);
            const float b0 = bias ? bias[col] : 0.0f;
            const float b1 = bias ? bias[col + 1] : 0.0f;
            float2 v0 = make_float2(acc[mt][j][0] + b0, acc[mt][j][1] + b1);
            float2 v1 = make_float2(acc[mt][j][2] + b0, acc[mt][j][3] + b1);
            *(float2*)(C + (size_t)row * Nn + col) = v0;
            *(float2*)(C + (size_t)(row + 8) * Nn + col) = v1;
        }
}

// merged QKV GEMM: bx<8 -> Q (all rows); bx>=8 -> KV (compacted rows)
__global__ void __launch_bounds__(512, 1) gemm_qkv(
    const __half* __restrict__ xh,
    const __half* __restrict__ wqh, const __half* __restrict__ wql,
    float* __restrict__ q_out, float* __restrict__ kv_out,
    const int* __restrict__ rowmap, const int* __restrict__ cnts)
{
    const int bx = blockIdx.x;
    if (bx < 8) {
        gemm_body(xh, wqh, wql, nullptr, q_out, C_, bx << 7, nullptr);
    } else {
        const int bm = blockIdx.y << 7;
        if ((bm & (N_ - 1)) >= cnts[bm >> 11]) return;
        gemm_body(xh, wqh + (size_t)C_ * C_, wql + (size_t)C_ * C_,
                  nullptr, kv_out, 2048, (bx - 8) << 7, rowmap);
    }
}

// plain GEMM (projection)
__global__ void __launch_bounds__(512, 1) gemm_std(
    const __half* __restrict__ A,
    const __half* __restrict__ Bh, const __half* __restrict__ Bl,
    const float* __restrict__ bias, float* __restrict__ C, int Nn)
{
    gemm_body(A, Bh, Bl, bias, C, Nn, blockIdx.x << 7, nullptr);
}

// ---------------- fused RoPE: blocks [0,M) = Q, [M,2M) = KV ------------------
__global__ void __launch_bounds__(512) rope_all()
{
    const int h = threadIdx.x >> 5;
    const int i = threadIdx.x & 31;
    float inv = exp2f(-11.0f * (float)i * (1.0f / 32.0f));  // 2048^(-i/32)

    if (blockIdx.x < M_) {
        // ---- Q path: round to fp16 ----
        const int m = blockIdx.x;
        const int b = m >> 11, n = m & (N_ - 1);
        const float* row = g_qkv + (size_t)m * C_;
        float q0 = row[h * D_ + i], q1 = row[h * D_ + i + 32];
        float th = (float)n * inv;
        float cs = cosf(th), sn = sinf(th);
        float qa = q0 * cs - q1 * sn, qb = q1 * cs + q0 * sn;

        size_t base = (((size_t)b * H_ + h) * N_ + n) * D_;
        g_qh[base + i]      = __float2half_rn(qa);
        g_qh[base + i + 32] = __float2half_rn(qb);
    } else {
        // ---- KV path (compacted rows): K, V hi/lo split ----
        const int m = blockIdx.x - M_;
        const int b = m >> 11, slot = m & (N_ - 1);
        if (slot >= g_kvcnt[b]) return;
        const int n = g_inv[m] & (N_ - 1);
        const float* row = g_qkv + (size_t)M_ * C_ + (size_t)m * 2048;
        float k0 = row[h * D_ + i],        k1 = row[h * D_ + i + 32];
        float v0 = row[C_ + h * D_ + i],   v1 = row[C_ + h * D_ + i + 32];
        float th = (float)n * inv;
        float cs = cosf(th), sn = sinf(th);
        float ka = k0 * cs - k1 * sn, kb = k1 * cs + k0 * sn;

        size_t base = (((size_t)b * H_ + h) * N_ + slot) * D_;
        const float vals[4] = {ka, kb, v0, v1};
        __half* Hp[4] = {g_kh + base + i, g_kh + base + i + 32,
                         g_vh + base + i, g_vh + base + i + 32};
        __half* Lp[4] = {g_kl + base + i, g_kl + base + i + 32,
                         g_vl + base + i, g_vl + base + i + 32};
#pragma unroll
        for (int t = 0; t < 4; t++) {
            __half hv = __float2half_rn(vals[t]);
            *Hp[t] = hv;
            *Lp[t] = __float2half_rn(vals[t] - __half2float(hv));
        }
    }
}

// ---------------- flash attention over COMPACTED keys, BQ=128 BKV=64 --------
// Q rounded fp16 (16KB); K split hi/lo, V split hi/lo (2 x 32KB stages).
#define AT_KV0  16384
#define AT_SMEM (16384 + 65536 + 512)

__global__ void __launch_bounds__(256, 1) flash_attn_mma()
{
    const int tid = threadIdx.x, lane = tid & 31, w = tid >> 5;
    const int b = blockIdx.z, h = blockIdx.y;
    const int q0 = blockIdx.x << 7;
    const uint32_t sb = smem_u32(dyn_sm);
    const size_t hoff = ((size_t)b * H_ + h) * N_ * D_;
    float* mbuf = (float*)(dyn_sm + 16384 + 65536);

    const int cnt = g_kvcnt[b];
    int nkv = (cnt + 63) >> 6;
    if (nkv < 1) nkv = 1;

    // stage Q fp16 [128][64]
    {
        const __half* qsrc = g_qh + hoff + (size_t)q0 * D_;
#pragma unroll
        for (int i = 0; i < 4; i++) {
            const int g = tid + i * 256;          // 1024 granules
            const int row = g >> 3, dg = g & 7;
            uint4 v = *(const uint4*)(qsrc + row * 64 + dg * 8);
            *(uint4*)(dyn_sm + swz(row * 128 + dg * 16)) = v;
        }
    }

    const __half* ksrc[4] = {g_kh + hoff, g_kl + hoff, g_vh + hoff, g_vl + hoff};
    const __half* kgsrc[8];
    uint32_t ksdst[8];
#pragma unroll
    for (int i = 0; i < 8; i++) {
        const int gid = tid + i * 256;
        const int op = gid >> 9, g = gid & 511;
        const int row = g >> 3, dg = g & 7;
        kgsrc[i] = ksrc[op] + (size_t)row * D_ + dg * 8;
        ksdst[i] = AT_KV0 + op * 8192 + swz(row * 128 + dg * 16);
    }
    auto issue_kv = [&](int it) {
        const uint32_t stoff = (it & 1) * 32768;
#pragma unroll
        for (int i = 0; i < 8; i++)
            cp16(sb + stoff + ksdst[i], kgsrc[i] + it * 64 * D_);
        if (tid < 64)
            mbuf[(it & 1) * 64 + tid] = (it * 64 + tid < cnt) ? 0.0f : -1e9f;
    };

    issue_kv(0); CP_COMMIT();
    __syncthreads();

    // preload Q fragments
    uint32_t qf[4][4];
    {
        const int rowQ = w * 16 + (lane & 15);
        const uint32_t base = rowQ * 128 + (lane >> 4) * 16;
#pragma unroll
        for (int ks = 0; ks < 4; ks++)
            ldsm4(qf[ks], sb + swz(base + ks * 32));
    }

    float o[8][4];
#pragma unroll
    for (int j = 0; j < 8; j++)
#pragma unroll
        for (int q = 0; q < 4; q++) o[j][q] = 0.0f;
    float m0 = -INFINITY, m1 = -INFINITY, l0 = 0.0f, l1 = 0.0f;

    for (int it = 0; it < nkv; it++) {
        CP_WAIT(0);
        __syncthreads();
        if (it + 1 < nkv) issue_kv(it + 1);
        CP_COMMIT();

        const uint32_t kvb = sb + AT_KV0 + (it & 1) * 32768;
        const float* mb = mbuf + (it & 1) * 64;

        // ---- S = Q (Kh + Kl)^T : 2-pass ----
        float s[8][4];
#pragma unroll
        for (int j = 0; j < 8; j++)
#pragma unroll
            for (int q = 0; q < 4; q++) s[j][q] = 0.0f;

#pragma unroll
        for (int ks = 0; ks < 4; ks++) {
#pragma unroll
            for (int np = 0; np < 4; np++) {
                const int nB = np * 16 + (lane & 7) + ((lane >> 4) << 3);
                const uint32_t ob = nB * 128 + ((lane >> 3) & 1) * 16 + ks * 32;
                uint32_t kb_h[4], kb_l[4];
                ldsm4(kb_h, kvb + swz(ob));
                ldsm4(kb_l, kvb + 8192 + swz(ob));
                mma16816(s[2 * np],     qf[ks], kb_h[0], kb_h[1]);
                mma16816(s[2 * np + 1], qf[ks], kb_h[2], kb_h[3]);
                mma16816(s[2 * np],     qf[ks], kb_l[0], kb_l[1]);
                mma16816(s[2 * np + 1], qf[ks], kb_l[2], kb_l[3]);
            }
        }

        // ---- scale + tail mask + online softmax ----
        const float scale = 0.125f;
        float mx0 = -INFINITY, mx1 = -INFINITY;
#pragma unroll
        for (int j = 0; j < 8; j++) {
            const int col = j * 8 + ((lane & 3) << 1);
            const float mb0 = mb[col], mb1 = mb[col + 1];
            s[j][0] = fmaf(s[j][0], scale, mb0);
            s[j][1] = fmaf(s[j][1], scale, mb1);
            s[j][2] = fmaf(s[j][2], scale, mb0);
            s[j][3] = fmaf(s[j][3], scale, mb1);
            mx0 = fmaxf(mx0, fmaxf(s[j][0], s[j][1]));
            mx1 = fmaxf(mx1, fmaxf(s[j][2], s[j][3]));
        }
        mx0 = fmaxf(mx0, __shfl_xor_sync(0xffffffffu, mx0, 1));
        mx0 = fmaxf(mx0, __shfl_xor_sync(0xffffffffu, mx0, 2));
        mx1 = fmaxf(mx1, __shfl_xor_sync(0xffffffffu, mx1, 1));
        mx1 = fmaxf(mx1, __shfl_xor_sync(0xffffffffu, mx1, 2));
        const float mn0 = fmaxf(m0, mx0), mn1 = fmaxf(m1, mx1);
        const float a0 = __expf(m0 - mn0), a1 = __expf(m1 - mn1);
        m0 = mn0; m1 = mn1;
        float s0 = 0.0f, s1 = 0.0f;
#pragma unroll
        for (int j = 0; j < 8; j++) {
            s[j][0] = __expf(s[j][0] - mn0);
            s[j][1] = __expf(s[j][1] - mn0);
            s[j][2] = __expf(s[j][2] - mn1);
            s[j][3] = __expf(s[j][3] - mn1);
            s0 += s[j][0] + s[j][1];
            s1 += s[j][2] + s[j][3];
        }
        s0 += __shfl_xor_sync(0xffffffffu, s0, 1);
        s0 += __shfl_xor_sync(0xffffffffu, s0, 2);
        s1 += __shfl_xor_sync(0xffffffffu, s1, 1);
        s1 += __shfl_xor_sync(0xffffffffu, s1, 2);
        l0 = l0 * a0 + s0;
        l1 = l1 * a1 + s1;
#pragma unroll
        for (int j = 0; j < 8; j++) {
            o[j][0] *= a0; o[j][1] *= a0;
            o[j][2] *= a1; o[j][3] *= a1;
        }

        // ---- pack P fragments (rounded fp16, no lo) ----
        uint32_t ph[4][4];
#pragma unroll
        for (int kt = 0; kt < 4; kt++) {
            const int t0 = 2 * kt, t1 = 2 * kt + 1;
            ph[kt][0] = pack2h(s[t0][0], s[t0][1]);
            ph[kt][1] = pack2h(s[t0][2], s[t0][3]);
            ph[kt][2] = pack2h(s[t1][0], s[t1][1]);
            ph[kt][3] = pack2h(s[t1][2], s[t1][3]);
        }

        // ---- O += P (Vh + Vl) : 2-pass, V via ldmatrix.trans ----
#pragma unroll
        for (int kt = 0; kt < 4; kt++) {
#pragma unroll
            for (int dp = 0; dp < 4; dp++) {
                const int kvr = kt * 16 + (lane & 15);
                const uint32_t ob = kvr * 128 + (dp * 2 + (lane >> 4)) * 16;
                uint32_t v_h[4], v_l[4];
                ldsm4t(v_h, kvb + 16384 + swz(ob));
                ldsm4t(v_l, kvb + 24576 + swz(ob));
                mma16816(o[2 * dp],     ph[kt], v_h[0], v_h[1]);
                mma16816(o[2 * dp + 1], ph[kt], v_h[2], v_h[3]);
                mma16816(o[2 * dp],     ph[kt], v_l[0], v_l[1]);
                mma16816(o[2 * dp + 1], ph[kt], v_l[2], v_l[3]);
            }
        }
    }

    // ---- normalize + round fp16 -> g_aoh ----
    const float li0 = 1.0f / l0, li1 = 1.0f / l1;
    const int n0 = q0 + w * 16 + (lane >> 2);
    const size_t ro0 = (size_t)(b * N_ + n0) * C_ + h * D_;
    const size_t ro1 = ro0 + (size_t)8 * C_;
#pragma unroll
    for (int j = 0; j < 8; j++) {
        const int col = j * 8 + ((lane & 3) << 1);
        *(uint32_t*)(g_aoh + ro0 + col) = pack2h(o[j][0] * li0, o[j][1] * li0);
        *(uint32_t*)(g_aoh + ro1 + col) = pack2h(o[j][2] * li1, o[j][3] * li1);
    }
}

// ---------------------------------------------------------------------------
extern "C" void kernel_launch(void* const* d_in, const int* in_sizes, int n_in,
                              void* d_out, int out_size)
{
    const float* x      = (const float*)d_in[0];
    const float* w_qkv  = (const float*)d_in[1];
    const float* w_proj = (const float*)d_in[2];
    const float* b_proj = (const float*)d_in[3];
    const int*   kpm    = (const int*)d_in[4];
    float* out = (float*)d_out;

    float* qkv;
    __half *xh, *wqh, *wql, *wph, *wpl, *aoh;
    int *invp, *cntp;
    cudaGetSymbolAddress((void**)&qkv, g_qkv);
    cudaGetSymbolAddress((void**)&xh,  g_xh);
    cudaGetSymbolAddress((void**)&wqh, g_wqh);
    cudaGetSymbolAddress((void**)&wql, g_wql);
    cudaGetSymbolAddress((void**)&wph, g_wph);
    cudaGetSymbolAddress((void**)&wpl, g_wpl);
    cudaGetSymbolAddress((void**)&aoh, g_aoh);
    cudaGetSymbolAddress((void**)&invp,  g_inv);
    cudaGetSymbolAddress((void**)&cntp,  g_kvcnt);

    float* qkv_q  = qkv;                          // [M][1024]
    float* qkv_kv = qkv + (size_t)M_ * C_;        // [M][2048]

    // 0) key compaction scan + fused fp32 -> fp16 conversion
    compact_scan<<<B_, 256>>>(kpm);
    cvt_fp16<<<(CVT_TOT + 255) / 256, 256>>>(
        (const float4*)x,      (uint2*)xh,
        (const float4*)w_qkv,  (uint2*)wqh, (uint2*)wql,
        (const float4*)w_proj, (uint2*)wph, (uint2*)wpl);

    cudaFuncSetAttribute(gemm_qkv, cudaFuncAttributeMaxDynamicSharedMemorySize, G_SMEM);
    cudaFuncSetAttribute(gemm_std, cudaFuncAttributeMaxDynamicSharedMemorySize, G_SMEM);

    // 1) merged Q + KV gemm
    gemm_qkv<<<dim3(24, M_ / 128), 512, G_SMEM>>>(
        xh, wqh, wql, qkv_q, qkv_kv, invp, cntp);

    // 2) fused RoPE (Q + compacted KV)
    rope_all<<<2 * M_, 512>>>();

    // 3) flash attention over compacted keys
    cudaFuncSetAttribute(flash_attn_mma, cudaFuncAttributeMaxDynamicSharedMemorySize,
                         AT_SMEM);
    flash_attn_mma<<<dim3(N_ / 128, H_, B_), 256, AT_SMEM>>>();

    // 4) out = ao @ w_proj^T + b_proj
    gemm_std<<<dim3(C_ / 128, M_ / 128), 512, G_SMEM>>>(
        aoh, wph, wpl, b_proj, out, C_);
}